// round 8
// baseline (speedup 1.0000x reference)
#include <cuda_runtime.h>
#include <math.h>

#define N_ROWS 500000
#define TILE_M 64
#define N_TILES ((N_ROWS + TILE_M - 1) / TILE_M)   // 7813
#define TPB 256
#define NWARP 8
#define PGRID 152

typedef unsigned long long ull;

#define OUT_SCALAR ((size_t)N_ROWS * 100)

// ---------------- f32x2 helpers ----------------
__device__ __forceinline__ ull ffma2(ull a, ull b, ull c) {
    ull d;
    asm("fma.rn.f32x2 %0, %1, %2, %3;" : "=l"(d) : "l"(a), "l"(b), "l"(c));
    return d;
}
__device__ __forceinline__ float fold2(ull v) {
    float2 t = *reinterpret_cast<float2*>(&v);
    return t.x + t.y;
}

// ---------------- global accumulators + z2 scratch ----------------
__device__ double g_p0;
__device__ double g_sq;
__device__ double g_diff;
__device__ double g_mu[100];
__device__ float g_z2[(size_t)N_TILES * TILE_M * 64];   // [tile][row][64]

__global__ void init_kernel() {
    int t = threadIdx.x;
    if (t == 0) { g_p0 = 0.0; g_sq = 0.0; g_diff = 0.0; }
    if (t < 100) g_mu[t] = 0.0;
}

// ======== warp GEMM block: 32 rows x 16 cols, fp32x2 packed over k ========
// Lane (qr=lane>>2 0..7, qc=lane&3): rows rb+qr+8i, cols cb+qc+4j.
// A[row][k] (stride/4 odd), W[col][k] (stride/4 odd). K consumed in 4-float steps.
__device__ __forceinline__ void ffma_block(
    const float* __restrict__ W, int ws, const float* __restrict__ bias,
    const float* __restrict__ A0, int as0, int ks0,
    const float* __restrict__ A1, int as1, int ks1, int kofs1,
    float* __restrict__ outb, int os, bool relu,
    int rb, int cb, int qr, int qc)
{
    ull acc[4][4];
    #pragma unroll
    for (int i = 0; i < 4; i++)
    #pragma unroll
    for (int j = 0; j < 4; j++) acc[i][j] = 0ull;

    const float* wbase = W + (size_t)(cb + qc) * ws;

    // segment 0
    {
        const float* ap = A0 + (size_t)(rb + qr) * as0;
        const float* wp = wbase;
        #pragma unroll 2
        for (int s = 0; s < ks0; s++) {
            ulonglong2 av[4], bv[4];
            #pragma unroll
            for (int i = 0; i < 4; i++)
                av[i] = *(const ulonglong2*)(ap + (size_t)(8 * i) * as0);
            #pragma unroll
            for (int j = 0; j < 4; j++)
                bv[j] = *(const ulonglong2*)(wp + (size_t)(4 * j) * ws);
            #pragma unroll
            for (int i = 0; i < 4; i++)
            #pragma unroll
            for (int j = 0; j < 4; j++) {
                acc[i][j] = ffma2(av[i].x, bv[j].x, acc[i][j]);
                acc[i][j] = ffma2(av[i].y, bv[j].y, acc[i][j]);
            }
            ap += 4; wp += 4;
        }
    }
    // segment 1 (concat routing)
    if (ks1 > 0) {
        const float* ap = A1 + (size_t)(rb + qr) * as1;
        const float* wp = wbase + kofs1;
        #pragma unroll 2
        for (int s = 0; s < ks1; s++) {
            ulonglong2 av[4], bv[4];
            #pragma unroll
            for (int i = 0; i < 4; i++)
                av[i] = *(const ulonglong2*)(ap + (size_t)(8 * i) * as1);
            #pragma unroll
            for (int j = 0; j < 4; j++)
                bv[j] = *(const ulonglong2*)(wp + (size_t)(4 * j) * ws);
            #pragma unroll
            for (int i = 0; i < 4; i++)
            #pragma unroll
            for (int j = 0; j < 4; j++) {
                acc[i][j] = ffma2(av[i].x, bv[j].x, acc[i][j]);
                acc[i][j] = ffma2(av[i].y, bv[j].y, acc[i][j]);
            }
            ap += 4; wp += 4;
        }
    }
    // epilogue: fold + bias (+relu) -> smem
    #pragma unroll
    for (int i = 0; i < 4; i++) {
        int r = rb + qr + 8 * i;
        #pragma unroll
        for (int j = 0; j < 4; j++) {
            int c = cb + qc + 4 * j;
            float v = fold2(acc[i][j]) + bias[c];
            if (relu) v = fmaxf(v, 0.0f);
            outb[(size_t)r * os + c] = v;
        }
    }
}

__device__ __forceinline__ void run_layer(
    const float* __restrict__ W, int ws, const float* __restrict__ bias,
    const float* __restrict__ A0, int as0, int ks0,
    const float* __restrict__ A1, int as1, int ks1, int kofs1,
    float* __restrict__ outb, int os, int NT, bool relu, int warp, int lane)
{
    const int qr = lane >> 2, qc = lane & 3;
    for (int b = warp; b < 2 * NT; b += NWARP) {
        int rb = (b & 1) * 32, cb = (b >> 1) * 16;
        ffma_block(W, ws, bias, A0, as0, ks0, A1, as1, ks1, kofs1,
                   outb, os, relu, rb, cb, qr, qc);
    }
}

// ================= K1: layers 1,2 (persistent) =================
// word offsets; strides/4 all odd for conflict-free LDS.128
#define W1_OFS   0        // 112 x 212  (k: x 0-99 | h 100-199 | pad)
#define W12_OFS  23744    // 64 x 116   (k = z1 cols 0-111)
#define B1_OFS   31168    // 112
#define B12_OFS  31280    // 64
#define XS_OFS   31344    // 64 x 108
#define HS_OFS   38256    // 64 x 108
#define Z1_OFS   45168    // 64 x 116
#define Z2_OFS   52592    // 64 x 68
#define K1_WORDS 56944
#define K1_SMEM  (K1_WORDS * 4)

__global__ void __launch_bounds__(TPB, 1) k1(
    const float* __restrict__ x, const float* __restrict__ h,
    const float* __restrict__ w1, const float* __restrict__ b1,
    const float* __restrict__ w12, const float* __restrict__ b12)
{
    extern __shared__ float sm[];
    const int tid = threadIdx.x, lane = tid & 31, warp = tid >> 5;

    for (int i = tid; i < 31344; i += TPB) sm[i] = 0.0f;   // weights+bias zero
    __syncthreads();
    for (int i = tid; i < 20000; i += TPB) {
        int n = i / 200, k = i % 200;
        sm[W1_OFS + n * 212 + k] = w1[i];
    }
    for (int i = tid; i < 5000; i += TPB) {
        int n = i / 100, k = i % 100;
        sm[W12_OFS + n * 116 + k] = w12[i];
    }
    for (int i = tid; i < 100; i += TPB) sm[B1_OFS + i] = b1[i];
    for (int i = tid; i < 50;  i += TPB) sm[B12_OFS + i] = b12[i];
    __syncthreads();

    for (int tile = blockIdx.x; tile < N_TILES; tile += PGRID) {
        const size_t r0 = (size_t)tile * TILE_M;
        // stage x,h (zero-fill tail rows)
        for (int i = tid; i < TILE_M * 25; i += TPB) {
            int r = i / 25, c4 = (i % 25) * 4;
            size_t gr = r0 + r;
            float4 xv = make_float4(0.f, 0.f, 0.f, 0.f), hv = xv;
            if (gr < N_ROWS) {
                xv = *(const float4*)(x + gr * 100 + c4);
                hv = *(const float4*)(h + gr * 100 + c4);
            }
            *(float4*)(&sm[XS_OFS + r * 108 + c4]) = xv;
            *(float4*)(&sm[HS_OFS + r * 108 + c4]) = hv;
        }
        __syncthreads();
        // L1: [x|h] -> z1 (N=112 padded), K=100+100
        run_layer(sm + W1_OFS, 212, sm + B1_OFS,
                  sm + XS_OFS, 108, 25, sm + HS_OFS, 108, 25, 100,
                  sm + Z1_OFS, 116, 7, true, warp, lane);
        __syncthreads();
        // L2: z1 -> z2 (N=64 padded), K=112
        run_layer(sm + W12_OFS, 116, sm + B12_OFS,
                  sm + Z1_OFS, 116, 28, 0, 0, 0, 0,
                  sm + Z2_OFS, 68, 4, true, warp, lane);
        __syncthreads();
        // z2 -> gmem scratch
        float* zg = g_z2 + (size_t)tile * TILE_M * 64;
        for (int i = tid; i < TILE_M * 16; i += TPB) {
            int r = i / 16, c4 = (i % 16) * 4;
            *(float4*)(zg + r * 64 + c4) = *(const float4*)(&sm[Z2_OFS + r * 68 + c4]);
        }
        __syncthreads();
    }
}

// ================= K2: layers 3..6 + part0 (persistent) =================
#define W13_OFS  0        // 32 x 164  (k: z2 0-63 | h 64-163)
#define W14_OFS  5248     // 32 x 36   (k: z3 0-31)
#define W15_OFS  6400     // 48 x 132  (k: z4 0-31 | h 32-131)
#define W2_OFS   12736    // 112 x 52  (k: z5 0-47)
#define B13_OFS  18560    // 32
#define B14_OFS  18592    // 32
#define B15_OFS  18624    // 48
#define B2_OFS   18672    // 112
#define HS2_OFS  18784    // 64 x 108
#define Z2B_OFS  25696    // 64 x 68
#define Z3_OFS   30048    // 64 x 36
#define Z4_OFS   32352    // 64 x 36
#define Z5_OFS   34656    // 64 x 52
#define FS_OFS   37984    // 64 x 116
#define K2_WORDS 45408
#define K2_SMEM  (K2_WORDS * 4)

__global__ void __launch_bounds__(TPB, 1) k2(
    const float* __restrict__ x, const float* __restrict__ h,
    const float* __restrict__ w13, const float* __restrict__ b13,
    const float* __restrict__ w14, const float* __restrict__ b14,
    const float* __restrict__ w15, const float* __restrict__ b15,
    const float* __restrict__ w2,  const float* __restrict__ b2,
    float* __restrict__ out)
{
    extern __shared__ float sm[];
    const int tid = threadIdx.x, lane = tid & 31, warp = tid >> 5;

    for (int i = tid; i < 18784; i += TPB) sm[i] = 0.0f;
    __syncthreads();
    for (int i = tid; i < 4500; i += TPB) {        // w13 [30][150]
        int n = i / 150, k = i % 150;
        int kk = (k < 50) ? k : (k + 14);          // h starts at 64
        sm[W13_OFS + n * 164 + kk] = w13[i];
    }
    for (int i = tid; i < 600; i += TPB) {         // w14 [20][30]
        int n = i / 30, k = i % 30;
        sm[W14_OFS + n * 36 + k] = w14[i];
    }
    for (int i = tid; i < 4800; i += TPB) {        // w15 [40][120]
        int n = i / 120, k = i % 120;
        int kk = (k < 20) ? k : (k + 12);          // h starts at 32
        sm[W15_OFS + n * 132 + kk] = w15[i];
    }
    for (int i = tid; i < 4000; i += TPB) {        // w2 [100][40]
        int n = i / 40, k = i % 40;
        sm[W2_OFS + n * 52 + k] = w2[i];
    }
    for (int i = tid; i < 30;  i += TPB) sm[B13_OFS + i] = b13[i];
    for (int i = tid; i < 20;  i += TPB) sm[B14_OFS + i] = b14[i];
    for (int i = tid; i < 40;  i += TPB) sm[B15_OFS + i] = b15[i];
    for (int i = tid; i < 100; i += TPB) sm[B2_OFS + i] = b2[i];
    __syncthreads();

    float p0 = 0.0f;

    for (int tile = blockIdx.x; tile < N_TILES; tile += PGRID) {
        const size_t r0 = (size_t)tile * TILE_M;
        for (int i = tid; i < TILE_M * 25; i += TPB) {
            int r = i / 25, c4 = (i % 25) * 4;
            size_t gr = r0 + r;
            float4 hv = make_float4(0.f, 0.f, 0.f, 0.f);
            if (gr < N_ROWS) hv = *(const float4*)(h + gr * 100 + c4);
            *(float4*)(&sm[HS2_OFS + r * 108 + c4]) = hv;
        }
        const float* zg = g_z2 + (size_t)tile * TILE_M * 64;
        for (int i = tid; i < TILE_M * 16; i += TPB) {
            int r = i / 16, c4 = (i % 16) * 4;
            *(float4*)(&sm[Z2B_OFS + r * 68 + c4]) = *(const float4*)(zg + r * 64 + c4);
        }
        __syncthreads();
        // L3: [z2|h] -> z3 (N=32), K=64+100
        run_layer(sm + W13_OFS, 164, sm + B13_OFS,
                  sm + Z2B_OFS, 68, 16, sm + HS2_OFS, 108, 25, 64,
                  sm + Z3_OFS, 36, 2, true, warp, lane);
        __syncthreads();
        // L4: z3 -> z4 (N=32), K=32
        run_layer(sm + W14_OFS, 36, sm + B14_OFS,
                  sm + Z3_OFS, 36, 8, 0, 0, 0, 0,
                  sm + Z4_OFS, 36, 2, true, warp, lane);
        __syncthreads();
        // L5: [z4|h] -> z5 (N=48), K=32+100
        run_layer(sm + W15_OFS, 132, sm + B15_OFS,
                  sm + Z4_OFS, 36, 8, sm + HS2_OFS, 108, 25, 32,
                  sm + Z5_OFS, 52, 3, true, warp, lane);
        __syncthreads();
        // L6: z5 -> f (N=112, no relu) into smem F buffer
        run_layer(sm + W2_OFS, 52, sm + B2_OFS,
                  sm + Z5_OFS, 52, 12, 0, 0, 0, 0,
                  sm + FS_OFS, 116, 7, false, warp, lane);
        __syncthreads();
        // coalesced f store + fused part0
        for (int i = tid; i < TILE_M * 25; i += TPB) {
            int r = i / 25, c4 = (i % 25) * 4;
            size_t gr = r0 + r;
            if (gr < N_ROWS) {
                float4 v = *(const float4*)(&sm[FS_OFS + r * 116 + c4]);
                *(float4*)(out + gr * 100 + c4) = v;
                if (gr + 1 < N_ROWS) {
                    float4 xn = *(const float4*)(x + (gr + 1) * 100 + c4);
                    float d0 = v.x - xn.x, d1 = v.y - xn.y;
                    float d2 = v.z - xn.z, d3 = v.w - xn.w;
                    p0 += d0 * d0 + d1 * d1 + d2 * d2 + d3 * d3;
                }
            }
        }
        __syncthreads();
    }

    // block reduction of part0
    #pragma unroll
    for (int o = 16; o > 0; o >>= 1) p0 += __shfl_down_sync(0xffffffffu, p0, o);
    __shared__ float red[NWARP];
    if (lane == 0) red[warp] = p0;
    __syncthreads();
    if (tid == 0) {
        float acc = 0.0f;
        #pragma unroll
        for (int i = 0; i < NWARP; i++) acc += red[i];
        atomicAdd(&g_p0, (double)acc);
    }
}

// ---------------- h statistics ----------------
#define HS_ROWS 512
__global__ void h_stats(const float* __restrict__ h) {
    const int col = threadIdx.x;
    const long long r0 = (long long)blockIdx.x * HS_ROWS;
    long long r1 = r0 + HS_ROWS; if (r1 > N_ROWS) r1 = N_ROWS;

    float csum = 0.0f, sq = 0.0f, dif = 0.0f;
    if (col < 100 && r0 < N_ROWS) {
        float prev = h[r0 * 100 + col];
        csum = prev; sq = prev * prev;
        #pragma unroll 8
        for (long long r = r0 + 1; r < r1; ++r) {
            float v = h[r * 100 + col];
            csum += v;
            sq   = fmaf(v, v, sq);
            dif  += fabsf(v - prev);
            prev = v;
        }
        if (r1 < N_ROWS) {
            float v = h[r1 * 100 + col];
            dif += fabsf(v - prev);
        }
        atomicAdd(&g_mu[col], (double)csum);
    }

    __shared__ float ssq[128], sdf[128];
    ssq[threadIdx.x] = sq; sdf[threadIdx.x] = dif;
    __syncthreads();
    for (int off = 64; off > 0; off >>= 1) {
        if (threadIdx.x < off) {
            ssq[threadIdx.x] += ssq[threadIdx.x + off];
            sdf[threadIdx.x] += sdf[threadIdx.x + off];
        }
        __syncthreads();
    }
    if (threadIdx.x == 0) {
        atomicAdd(&g_sq,   (double)ssq[0]);
        atomicAdd(&g_diff, (double)sdf[0]);
    }
}

// ---------------- finalize ----------------
__global__ void finalize(float* __restrict__ out) {
    __shared__ double smd[128];
    const int t = threadIdx.x;
    smd[t] = (t < 100) ? fabs(g_mu[t] / (double)N_ROWS) : 0.0;
    __syncthreads();
    for (int off = 64; off > 0; off >>= 1) {
        if (t < off) smd[t] += smd[t + off];
        __syncthreads();
    }
    if (t == 0) {
        out[OUT_SCALAR + 0] = (float)(sqrt(g_p0) / (double)(N_ROWS - 1));
        out[OUT_SCALAR + 1] = (float)(smd[0] / 100.0);
        out[OUT_SCALAR + 2] = (float)fabs(g_sq / (double)N_ROWS / 100.0 - 1.0);
        out[OUT_SCALAR + 3] = (float)(g_diff / (double)(N_ROWS - 1) / 100.0);
    }
}

// ---------------- launch ----------------
extern "C" void kernel_launch(void* const* d_in, const int* in_sizes, int n_in,
                              void* d_out, int out_size) {
    const float* x   = (const float*)d_in[0];
    const float* h   = (const float*)d_in[1];
    const float* w1  = (const float*)d_in[2];
    const float* b1  = (const float*)d_in[3];
    const float* w12 = (const float*)d_in[4];
    const float* b12 = (const float*)d_in[5];
    const float* w13 = (const float*)d_in[6];
    const float* b13 = (const float*)d_in[7];
    const float* w14 = (const float*)d_in[8];
    const float* b14 = (const float*)d_in[9];
    const float* w15 = (const float*)d_in[10];
    const float* b15 = (const float*)d_in[11];
    const float* w2  = (const float*)d_in[12];
    const float* b2  = (const float*)d_in[13];
    float* out = (float*)d_out;

    (void)in_sizes; (void)n_in; (void)out_size;

    cudaFuncSetAttribute(k1, cudaFuncAttributeMaxDynamicSharedMemorySize, K1_SMEM);
    cudaFuncSetAttribute(k2, cudaFuncAttributeMaxDynamicSharedMemorySize, K2_SMEM);

    init_kernel<<<1, 128>>>();
    k1<<<PGRID, TPB, K1_SMEM>>>(x, h, w1, b1, w12, b12);
    k2<<<PGRID, TPB, K2_SMEM>>>(x, h, w13, b13, w14, b14, w15, b15, w2, b2, out);
    h_stats<<<(N_ROWS + HS_ROWS - 1) / HS_ROWS, 128>>>(h);
    finalize<<<1, 128>>>(out);
}

// round 10
// speedup vs baseline: 1.9446x; 1.9446x over previous
#include <cuda_runtime.h>
#include <math.h>
#include <stdint.h>

#define N_ROWS 500000
#define TILE_M 64
#define N_TILES ((N_ROWS + TILE_M - 1) / TILE_M)   // 7813
#define TPB 512
#define NWARP 16
#define PGRID 148

typedef unsigned int u32;

#define OUT_SCALAR ((size_t)N_ROWS * 100)

// ---------------- global accumulators + z2 scratch ----------------
__device__ double g_p0;
__device__ double g_sq;
__device__ double g_diff;
__device__ double g_mu[100];
__device__ float g_z2[(size_t)N_TILES * TILE_M * 64];   // [tile][row][64]

__global__ void init_kernel() {
    int t = threadIdx.x;
    if (t == 0) { g_p0 = 0.0; g_sq = 0.0; g_diff = 0.0; }
    if (t < 100) g_mu[t] = 0.0;
}

// ---------------- tf32 / mma helpers ----------------
__device__ __forceinline__ u32 tf32c(float f) {
    u32 r; asm("cvt.rna.tf32.f32 %0, %1;" : "=r"(r) : "f"(f)); return r;
}
__device__ __forceinline__ void mma8(float* d, u32 a0, u32 a1, u32 a2, u32 a3,
                                     u32 b0, u32 b1) {
    asm("mma.sync.aligned.m16n8k8.row.col.f32.tf32.tf32.f32 "
        "{%0,%1,%2,%3}, {%4,%5,%6,%7}, {%8,%9}, {%0,%1,%2,%3};"
        : "+f"(d[0]), "+f"(d[1]), "+f"(d[2]), "+f"(d[3])
        : "r"(a0), "r"(a1), "r"(a2), "r"(a3), "r"(b0), "r"(b1));
}

// One k-segment of a 16-row x 16-col warp block, alternating accumulator
// sets c0/c1 (chain-split for ILP). A[row][k], W[n][k], smem tf32 bits.
__device__ __forceinline__ void mma_seg16(
    float c0[2][4], float c1[2][4],
    const u32* __restrict__ W, int ws,
    const u32* __restrict__ A, int as,
    int nsteps, int k0w,
    int rb, int cb, int qr, int qc)
{
    const u32* ap  = A + (size_t)(rb + qr) * as + qc;
    const u32* bp0 = W + (size_t)(cb + qr) * ws + k0w + qc;
    const u32* bp1 = bp0 + 8 * ws;
    const int as8 = 8 * as;
    int s = 0;
    for (; s + 1 < nsteps; s += 2) {
        {
            u32 a0 = ap[0], a1 = ap[as8], a2 = ap[4], a3 = ap[as8 + 4];
            u32 b00 = bp0[0], b01 = bp0[4], b10 = bp1[0], b11 = bp1[4];
            mma8(c0[0], a0, a1, a2, a3, b00, b01);
            mma8(c0[1], a0, a1, a2, a3, b10, b11);
            ap += 8; bp0 += 8; bp1 += 8;
        }
        {
            u32 a0 = ap[0], a1 = ap[as8], a2 = ap[4], a3 = ap[as8 + 4];
            u32 b00 = bp0[0], b01 = bp0[4], b10 = bp1[0], b11 = bp1[4];
            mma8(c1[0], a0, a1, a2, a3, b00, b01);
            mma8(c1[1], a0, a1, a2, a3, b10, b11);
            ap += 8; bp0 += 8; bp1 += 8;
        }
    }
    if (s < nsteps) {
        u32 a0 = ap[0], a1 = ap[as8], a2 = ap[4], a3 = ap[as8 + 4];
        u32 b00 = bp0[0], b01 = bp0[4], b10 = bp1[0], b11 = bp1[4];
        mma8(c0[0], a0, a1, a2, a3, b00, b01);
        mma8(c0[1], a0, a1, a2, a3, b10, b11);
    }
}

// Full block: up to two k-segments (concat routing) + bias/relu epilogue.
__device__ __forceinline__ void gemm_block16(
    const u32* __restrict__ W, int ws, const float* __restrict__ bias,
    const u32* __restrict__ A0, int as0, int ks0,
    const u32* __restrict__ A1, int as1, int ks1, int kofs1,
    u32* __restrict__ outb, int os, bool relu,
    int rb, int cb, int qr, int qc)
{
    float c0[2][4] = {}, c1[2][4] = {};
    mma_seg16(c0, c1, W, ws, A0, as0, ks0, 0, rb, cb, qr, qc);
    if (ks1 > 0)
        mma_seg16(c0, c1, W, ws, A1, as1, ks1, kofs1, rb, cb, qr, qc);

    #pragma unroll
    for (int ni = 0; ni < 2; ni++) {
        int col = cb + ni * 8 + 2 * qc;
        float b0v = bias[col], b1v = bias[col + 1];
        float v0 = c0[ni][0] + c1[ni][0] + b0v;
        float v1 = c0[ni][1] + c1[ni][1] + b1v;
        float v2 = c0[ni][2] + c1[ni][2] + b0v;
        float v3 = c0[ni][3] + c1[ni][3] + b1v;
        if (relu) {
            v0 = fmaxf(v0, 0.0f); v1 = fmaxf(v1, 0.0f);
            v2 = fmaxf(v2, 0.0f); v3 = fmaxf(v3, 0.0f);
        }
        int r = rb + qr;
        *(uint2*)(outb + (size_t)r * os + col)       = make_uint2(tf32c(v0), tf32c(v1));
        *(uint2*)(outb + (size_t)(r + 8) * os + col) = make_uint2(tf32c(v2), tf32c(v3));
    }
}

__device__ __forceinline__ void run_layer(
    u32* sm, float* smf, int warp, int lane,
    int wofs, int ws, int bofs,
    int a0ofs, int as0, int ks0, int a1ofs, int as1, int ks1, int kofs1,
    int oofs, int os, int NT16, bool relu)
{
    const int qr = lane >> 2, qc = lane & 3;
    const int nblocks = 4 * NT16;
    for (int b = warp; b < nblocks; b += NWARP) {
        int rb = (b & 3) * 16, cb = (b >> 2) * 16;
        gemm_block16(sm + wofs, ws, smf + bofs,
                     sm + a0ofs, as0, ks0, sm + a1ofs, as1, ks1, kofs1,
                     sm + oofs, os, relu, rb, cb, qr, qc);
    }
}

// ================= K1: layers 1,2 (persistent) =================
#define W1_OFS   0        // 112 x 212  (k: x 0-99 | h 104-203)
#define W12_OFS  23744    // 64 x 116   (k: z1 0-111)
#define B1_OFS   31168    // 112
#define B12_OFS  31280    // 64
#define XS_OFS   31344    // 64 x 108
#define HS_OFS   38256    // 64 x 108
#define Z1_OFS   45168    // 64 x 116
#define Z2_OFS   52592    // 64 x 68
#define K1_WORDS 56944
#define K1_SMEM  (K1_WORDS * 4)

__global__ void __launch_bounds__(TPB, 1) k1(
    const float* __restrict__ x, const float* __restrict__ h,
    const float* __restrict__ w1, const float* __restrict__ b1,
    const float* __restrict__ w12, const float* __restrict__ b12)
{
    extern __shared__ u32 sm[];
    float* smf = (float*)sm;
    const int tid = threadIdx.x, lane = tid & 31, warp = tid >> 5;

    for (int i = tid; i < 31344; i += TPB) sm[i] = 0u;   // weights+bias zero
    __syncthreads();
    for (int i = tid; i < 20000; i += TPB) {
        int n = i / 200, k = i % 200;
        int kk = (k < 100) ? k : k + 4;
        sm[W1_OFS + n * 212 + kk] = tf32c(w1[i]);
    }
    for (int i = tid; i < 5000; i += TPB) {
        int n = i / 100, k = i % 100;
        sm[W12_OFS + n * 116 + k] = tf32c(w12[i]);
    }
    for (int i = tid; i < 100; i += TPB) smf[B1_OFS + i] = b1[i];
    for (int i = tid; i < 50;  i += TPB) smf[B12_OFS + i] = b12[i];
    __syncthreads();

    for (int tile = blockIdx.x; tile < N_TILES; tile += PGRID) {
        const size_t r0 = (size_t)tile * TILE_M;
        // stage x,h (tf32; zero pads + tail rows)
        for (int i = tid; i < TILE_M * 27; i += TPB) {
            int r = i / 27, c4 = (i % 27) * 4;
            size_t gr = r0 + r;
            float4 xv = make_float4(0.f, 0.f, 0.f, 0.f), hv = xv;
            if (gr < N_ROWS && c4 < 100) {
                xv = *(const float4*)(x + gr * 100 + c4);
                hv = *(const float4*)(h + gr * 100 + c4);
            }
            uint4 xo, ho;
            xo.x = tf32c(xv.x); xo.y = tf32c(xv.y); xo.z = tf32c(xv.z); xo.w = tf32c(xv.w);
            ho.x = tf32c(hv.x); ho.y = tf32c(hv.y); ho.z = tf32c(hv.z); ho.w = tf32c(hv.w);
            *(uint4*)(sm + XS_OFS + r * 108 + c4) = xo;
            *(uint4*)(sm + HS_OFS + r * 108 + c4) = ho;
        }
        __syncthreads();
        // L1: [x|h] -> z1 (N=112), K = 13+13 steps
        run_layer(sm, smf, warp, lane, W1_OFS, 212, B1_OFS,
                  XS_OFS, 108, 13, HS_OFS, 108, 13, 104,
                  Z1_OFS, 116, 7, true);
        __syncthreads();
        // L2: z1 -> z2 (N=64), K = 14 steps
        run_layer(sm, smf, warp, lane, W12_OFS, 116, B12_OFS,
                  Z1_OFS, 116, 14, 0, 0, 0, 0,
                  Z2_OFS, 68, 4, true);
        __syncthreads();
        // z2 -> gmem scratch (values already tf32-rounded floats)
        float* zg = g_z2 + (size_t)tile * TILE_M * 64;
        for (int i = tid; i < TILE_M * 16; i += TPB) {
            int r = i / 16, c4 = (i % 16) * 4;
            *(float4*)(zg + r * 64 + c4) = *(const float4*)(sm + Z2_OFS + r * 68 + c4);
        }
        __syncthreads();
    }
}

// ================= K2: layers 3..6 + part0 (persistent) =================
#define W13_OFS  0        // 32 x 164  (k: z2 0-49 | h 56-155)
#define W14_OFS  5248     // 32 x 36   (k: z3 0-29)
#define W15_OFS  6400     // 48 x 132  (k: z4 0-19 | h 24-123)
#define W2_OFS   12736    // 112 x 52  (k: z5 0-39)
#define B13_OFS  18560    // 32
#define B14_OFS  18592    // 32
#define B15_OFS  18624    // 48
#define B2_OFS   18672    // 112
#define HS2_OFS  18784    // 64 x 108
#define Z2B_OFS  25696    // 64 x 68
#define Z3_OFS   30048    // 64 x 36
#define Z4_OFS   32352    // 64 x 36
#define Z5_OFS   34656    // 64 x 52
#define K2_WORDS 37984
#define K2_SMEM  (K2_WORDS * 4)

__global__ void __launch_bounds__(TPB, 1) k2(
    const float* __restrict__ x, const float* __restrict__ h,
    const float* __restrict__ w13, const float* __restrict__ b13,
    const float* __restrict__ w14, const float* __restrict__ b14,
    const float* __restrict__ w15, const float* __restrict__ b15,
    const float* __restrict__ w2,  const float* __restrict__ b2,
    float* __restrict__ out)
{
    extern __shared__ u32 sm[];
    float* smf = (float*)sm;
    const int tid = threadIdx.x, lane = tid & 31, warp = tid >> 5;
    const int qr = lane >> 2, qc = lane & 3;

    for (int i = tid; i < 18784; i += TPB) sm[i] = 0u;
    __syncthreads();
    for (int i = tid; i < 4500; i += TPB) {        // w13 [30][150]
        int n = i / 150, k = i % 150;
        int kk = (k < 50) ? k : 56 + (k - 50);     // h at 56..155
        sm[W13_OFS + n * 164 + kk] = tf32c(w13[i]);
    }
    for (int i = tid; i < 600; i += TPB) {         // w14 [20][30]
        int n = i / 30, k = i % 30;
        sm[W14_OFS + n * 36 + k] = tf32c(w14[i]);
    }
    for (int i = tid; i < 4800; i += TPB) {        // w15 [40][120]
        int n = i / 120, k = i % 120;
        int kk = (k < 20) ? k : 24 + (k - 20);     // h at 24..123
        sm[W15_OFS + n * 132 + kk] = tf32c(w15[i]);
    }
    for (int i = tid; i < 4000; i += TPB) {        // w2 [100][40]
        int n = i / 40, k = i % 40;
        sm[W2_OFS + n * 52 + k] = tf32c(w2[i]);
    }
    for (int i = tid; i < 30;  i += TPB) smf[B13_OFS + i] = b13[i];
    for (int i = tid; i < 20;  i += TPB) smf[B14_OFS + i] = b14[i];
    for (int i = tid; i < 40;  i += TPB) smf[B15_OFS + i] = b15[i];
    for (int i = tid; i < 100; i += TPB) smf[B2_OFS + i] = b2[i];
    __syncthreads();

    float p0 = 0.0f;

    for (int tile = blockIdx.x; tile < N_TILES; tile += PGRID) {
        const size_t r0 = (size_t)tile * TILE_M;
        for (int i = tid; i < TILE_M * 27; i += TPB) {
            int r = i / 27, c4 = (i % 27) * 4;
            size_t gr = r0 + r;
            float4 hv = make_float4(0.f, 0.f, 0.f, 0.f);
            if (gr < N_ROWS && c4 < 100) hv = *(const float4*)(h + gr * 100 + c4);
            uint4 ho;
            ho.x = tf32c(hv.x); ho.y = tf32c(hv.y); ho.z = tf32c(hv.z); ho.w = tf32c(hv.w);
            *(uint4*)(sm + HS2_OFS + r * 108 + c4) = ho;
        }
        const float* zg = g_z2 + (size_t)tile * TILE_M * 64;
        for (int i = tid; i < TILE_M * 16; i += TPB) {
            int r = i / 16, c4 = (i % 16) * 4;
            *(float4*)(sm + Z2B_OFS + r * 68 + c4) = *(const float4*)(zg + r * 64 + c4);
        }
        __syncthreads();
        // L3: [z2|h] -> z3 (N=32), K = 7+13 steps
        run_layer(sm, smf, warp, lane, W13_OFS, 164, B13_OFS,
                  Z2B_OFS, 68, 7, HS2_OFS, 108, 13, 56,
                  Z3_OFS, 36, 2, true);
        __syncthreads();
        // L4: z3 -> z4 (N=32), K = 4 steps
        run_layer(sm, smf, warp, lane, W14_OFS, 36, B14_OFS,
                  Z3_OFS, 36, 4, 0, 0, 0, 0,
                  Z4_OFS, 36, 2, true);
        __syncthreads();
        // L5: [z4|h] -> z5 (N=48), K = 3+13 steps
        run_layer(sm, smf, warp, lane, W15_OFS, 132, B15_OFS,
                  Z4_OFS, 36, 3, HS2_OFS, 108, 13, 24,
                  Z5_OFS, 52, 3, true);
        __syncthreads();
        // L6: z5 -> f (N=112 padded, no relu), K = 6 steps; direct store + part0
        for (int b = warp; b < 28; b += NWARP) {
            int rb = (b & 3) * 16, cb = (b >> 2) * 16;
            float c0[2][4] = {}, c1[2][4] = {};
            mma_seg16(c0, c1, sm + W2_OFS, 52, sm + Z5_OFS, 52, 6, 0,
                      rb, cb, qr, qc);
            #pragma unroll
            for (int ni = 0; ni < 2; ni++) {
                int col = cb + ni * 8 + 2 * qc;
                if (col >= 100) continue;
                float b0v = smf[B2_OFS + col], b1v = smf[B2_OFS + col + 1];
                #pragma unroll
                for (int hh = 0; hh < 2; hh++) {
                    size_t grow = r0 + rb + qr + hh * 8;
                    float v0 = c0[ni][2 * hh]     + c1[ni][2 * hh]     + b0v;
                    float v1 = c0[ni][2 * hh + 1] + c1[ni][2 * hh + 1] + b1v;
                    if (grow < N_ROWS) {
                        *(float2*)(out + grow * 100 + col) = make_float2(v0, v1);
                        if (grow + 1 < N_ROWS) {
                            float2 xn = *(const float2*)(x + (grow + 1) * 100 + col);
                            float d0 = v0 - xn.x, d1 = v1 - xn.y;
                            p0 += d0 * d0 + d1 * d1;
                        }
                    }
                }
            }
        }
        __syncthreads();
    }

    // block reduction of part0
    #pragma unroll
    for (int o = 16; o > 0; o >>= 1) p0 += __shfl_down_sync(0xffffffffu, p0, o);
    __shared__ float red[NWARP];
    if (lane == 0) red[warp] = p0;
    __syncthreads();
    if (tid == 0) {
        float acc = 0.0f;
        #pragma unroll
        for (int i = 0; i < NWARP; i++) acc += red[i];
        atomicAdd(&g_p0, (double)acc);
    }
}

// ---------------- h statistics ----------------
#define HS_ROWS 512
__global__ void h_stats(const float* __restrict__ h) {
    const int col = threadIdx.x;
    const long long r0 = (long long)blockIdx.x * HS_ROWS;
    long long r1 = r0 + HS_ROWS; if (r1 > N_ROWS) r1 = N_ROWS;

    float csum = 0.0f, sq = 0.0f, dif = 0.0f;
    if (col < 100 && r0 < N_ROWS) {
        float prev = h[r0 * 100 + col];
        csum = prev; sq = prev * prev;
        #pragma unroll 8
        for (long long r = r0 + 1; r < r1; ++r) {
            float v = h[r * 100 + col];
            csum += v;
            sq = fmaf(v, v, sq);
            dif += fabsf(v - prev);
            prev = v;
        }
        if (r1 < N_ROWS) dif += fabsf(h[r1 * 100 + col] - prev);
        atomicAdd(&g_mu[col], (double)csum);
    }
    __shared__ float ssq[128], sdf[128];
    ssq[threadIdx.x] = sq; sdf[threadIdx.x] = dif;
    __syncthreads();
    for (int off = 64; off > 0; off >>= 1) {
        if (threadIdx.x < off) {
            ssq[threadIdx.x] += ssq[threadIdx.x + off];
            sdf[threadIdx.x] += sdf[threadIdx.x + off];
        }
        __syncthreads();
    }
    if (threadIdx.x == 0) {
        atomicAdd(&g_sq, (double)ssq[0]);
        atomicAdd(&g_diff, (double)sdf[0]);
    }
}

// ---------------- finalize ----------------
__global__ void finalize(float* __restrict__ out) {
    __shared__ double smd[128];
    const int t = threadIdx.x;
    smd[t] = (t < 100) ? fabs(g_mu[t] / (double)N_ROWS) : 0.0;
    __syncthreads();
    for (int off = 64; off > 0; off >>= 1) {
        if (t < off) smd[t] += smd[t + off];
        __syncthreads();
    }
    if (t == 0) {
        out[OUT_SCALAR + 0] = (float)(sqrt(g_p0) / (double)(N_ROWS - 1));
        out[OUT_SCALAR + 1] = (float)(smd[0] / 100.0);
        out[OUT_SCALAR + 2] = (float)fabs(g_sq / (double)N_ROWS / 100.0 - 1.0);
        out[OUT_SCALAR + 3] = (float)(g_diff / (double)(N_ROWS - 1) / 100.0);
    }
}

// ---------------- launch ----------------
extern "C" void kernel_launch(void* const* d_in, const int* in_sizes, int n_in,
                              void* d_out, int out_size) {
    const float* x   = (const float*)d_in[0];
    const float* h   = (const float*)d_in[1];
    const float* w1  = (const float*)d_in[2];
    const float* b1  = (const float*)d_in[3];
    const float* w12 = (const float*)d_in[4];
    const float* b12 = (const float*)d_in[5];
    const float* w13 = (const float*)d_in[6];
    const float* b13 = (const float*)d_in[7];
    const float* w14 = (const float*)d_in[8];
    const float* b14 = (const float*)d_in[9];
    const float* w15 = (const float*)d_in[10];
    const float* b15 = (const float*)d_in[11];
    const float* w2  = (const float*)d_in[12];
    const float* b2  = (const float*)d_in[13];
    float* out = (float*)d_out;

    (void)in_sizes; (void)n_in; (void)out_size;

    cudaFuncSetAttribute(k1, cudaFuncAttributeMaxDynamicSharedMemorySize, K1_SMEM);
    cudaFuncSetAttribute(k2, cudaFuncAttributeMaxDynamicSharedMemorySize, K2_SMEM);

    init_kernel<<<1, 128>>>();
    k1<<<PGRID, TPB, K1_SMEM>>>(x, h, w1, b1, w12, b12);
    k2<<<PGRID, TPB, K2_SMEM>>>(x, h, w13, b13, w14, b14, w15, b15, w2, b2, out);
    h_stats<<<(N_ROWS + HS_ROWS - 1) / HS_ROWS, 128>>>(h);
    finalize<<<1, 128>>>(out);
}

// round 11
// speedup vs baseline: 2.5656x; 1.3194x over previous
#include <cuda_runtime.h>
#include <cuda_fp16.h>
#include <math.h>

#define N_ROWS 500000
#define TILE_M 128
#define N_TILES ((N_ROWS + TILE_M - 1) / TILE_M)   // 3907
#define TPB 512
#define NWARP 16
#define PGRID 148

typedef unsigned int u32;
typedef unsigned short u16;

#define OUT_SCALAR ((size_t)N_ROWS * 100)

// ---------------- global accumulators ----------------
__device__ double g_p0;
__device__ double g_sq;
__device__ double g_diff;
__device__ double g_mu[100];

__global__ void init_kernel() {
    int t = threadIdx.x;
    if (t == 0) { g_p0 = 0.0; g_sq = 0.0; g_diff = 0.0; }
    if (t < 100) g_mu[t] = 0.0;
}

// ---------------- fp16 / mma helpers ----------------
__device__ __forceinline__ u32 pack_h2(float a, float b) {
    __half2 t = __floats2half2_rn(a, b);        // x=a (low), y=b (high)
    return *reinterpret_cast<u32*>(&t);
}
__device__ __forceinline__ void mma16(float* d, u32 a0, u32 a1, u32 a2, u32 a3,
                                      u32 b0, u32 b1) {
    asm("mma.sync.aligned.m16n8k16.row.col.f32.f16.f16.f32 "
        "{%0,%1,%2,%3}, {%4,%5,%6,%7}, {%8,%9}, {%0,%1,%2,%3};"
        : "+f"(d[0]), "+f"(d[1]), "+f"(d[2]), "+f"(d[3])
        : "r"(a0), "r"(a1), "r"(a2), "r"(a3), "r"(b0), "r"(b1));
}

// One k-segment of a 16x16 warp block; A[row][k] fp16, W[n][k] fp16, both in
// smem as u32 words (2 fp16/word). as/ws/k0w in u32 units; step = 16 fp16 = 8 u32.
// Chain-split across steps into accumulator sets c0/c1 (summed in epilogue).
__device__ __forceinline__ void mma_seg(
    float c0[2][4], float c1[2][4],
    const u32* __restrict__ W, int ws,
    const u32* __restrict__ A, int as,
    int nsteps, int k0w,
    int rb, int cb, int qr, int qc)
{
    const u32* ap  = A + (size_t)(rb + qr) * as + qc;
    const u32* bp0 = W + (size_t)(cb + qr) * ws + k0w + qc;
    const u32* bp1 = bp0 + 8 * ws;
    const int as8 = 8 * as;
    int s = 0;
    for (; s + 1 < nsteps; s += 2) {
        {
            u32 a0 = ap[0], a1 = ap[as8], a2 = ap[4], a3 = ap[as8 + 4];
            u32 b00 = bp0[0], b01 = bp0[4], b10 = bp1[0], b11 = bp1[4];
            mma16(c0[0], a0, a1, a2, a3, b00, b01);
            mma16(c0[1], a0, a1, a2, a3, b10, b11);
            ap += 8; bp0 += 8; bp1 += 8;
        }
        {
            u32 a0 = ap[0], a1 = ap[as8], a2 = ap[4], a3 = ap[as8 + 4];
            u32 b00 = bp0[0], b01 = bp0[4], b10 = bp1[0], b11 = bp1[4];
            mma16(c1[0], a0, a1, a2, a3, b00, b01);
            mma16(c1[1], a0, a1, a2, a3, b10, b11);
            ap += 8; bp0 += 8; bp1 += 8;
        }
    }
    if (s < nsteps) {
        u32 a0 = ap[0], a1 = ap[as8], a2 = ap[4], a3 = ap[as8 + 4];
        u32 b00 = bp0[0], b01 = bp0[4], b10 = bp1[0], b11 = bp1[4];
        mma16(c0[0], a0, a1, a2, a3, b00, b01);
        mma16(c0[1], a0, a1, a2, a3, b10, b11);
    }
}

// ---------------- smem layout (u32 words) ----------------
#define W1_OFS   0        // 112n x 108w (fp16 k: x 0-99 | h 100-199 | pad)
#define W12_OFS  12096    // 64n x 60w   (k: z1 0-111)
#define W13_OFS  15936    // 32n x 92w   (k: z2 0-63 | h 64-163 | pad)
#define W14_OFS  18880    // 32n x 20w   (k: z3 0-31)
#define W15_OFS  19520    // 48n x 76w   (k: z4 0-31 | h 32-143)
#define W2_OFS   23168    // 112n x 28w  (k: z5 0-47)
#define B1_OFS   26304    // fp32 112
#define B12_OFS  26416    // 64
#define B13_OFS  26480    // 32
#define B14_OFS  26512    // 32
#define B15_OFS  26544    // 48
#define B2_OFS   26592    // 112
#define A_OFS    26704    // 128r x 108w (fp16 k: x 0-99 | h 100-199 | pad 200-215)
#define Z1_OFS   40528    // 128r x 60w  (N=112)
#define Z3_OFS   40528    // reuse z1: 128r x 20w (N=32)
#define Z4_OFS   43088    // reuse z1: 128r x 20w (N=32)
#define Z2_OFS   48208    // 128r x 36w  (N=64)
#define Z5_OFS   52816    // 128r x 28w  (N=48)
#define SM_WORDS 56400
#define SMEM_B   (SM_WORDS * 4)   // 225,600 B

// hidden-layer block: two k-segments + bias/relu epilogue packed to fp16
__device__ __forceinline__ void gemm_block(
    const u32* __restrict__ W, int ws, const float* __restrict__ bias,
    const u32* __restrict__ A0, int as0, int ks0,
    const u32* __restrict__ A1, int as1, int ks1, int k0w1,
    u32* __restrict__ outb, int os,
    int rb, int cb, int qr, int qc)
{
    float c0[2][4] = {}, c1[2][4] = {};
    mma_seg(c0, c1, W, ws, A0, as0, ks0, 0, rb, cb, qr, qc);
    if (ks1 > 0)
        mma_seg(c0, c1, W, ws, A1, as1, ks1, k0w1, rb, cb, qr, qc);

    #pragma unroll
    for (int ni = 0; ni < 2; ni++) {
        int col = cb + ni * 8 + 2 * qc;
        float b0v = bias[col], b1v = bias[col + 1];
        float v0 = fmaxf(c0[ni][0] + c1[ni][0] + b0v, 0.0f);
        float v1 = fmaxf(c0[ni][1] + c1[ni][1] + b1v, 0.0f);
        float v2 = fmaxf(c0[ni][2] + c1[ni][2] + b0v, 0.0f);
        float v3 = fmaxf(c0[ni][3] + c1[ni][3] + b1v, 0.0f);
        outb[(size_t)(rb + qr) * os + (col >> 1)]     = pack_h2(v0, v1);
        outb[(size_t)(rb + qr + 8) * os + (col >> 1)] = pack_h2(v2, v3);
    }
}

__device__ __forceinline__ void run_layer(
    u32* sm, float* smf, int warp, int lane,
    int wofs, int ws, int bofs,
    int a0ofs, int as0, int ks0, int a1ofs, int as1, int ks1, int k0w1,
    int oofs, int os, int NT)
{
    const int qr = lane >> 2, qc = lane & 3;
    const int nblocks = 8 * NT;
    for (int b = warp; b < nblocks; b += NWARP) {
        int rb = (b & 7) * 16, cb = (b >> 3) * 16;
        gemm_block(sm + wofs, ws, smf + bofs,
                   sm + a0ofs, as0, ks0, sm + a1ofs, as1, ks1, k0w1,
                   sm + oofs, os, rb, cb, qr, qc);
    }
}

// ================= fused MLP: all 6 layers, persistent =================
__global__ void __launch_bounds__(TPB, 1) fused(
    const float* __restrict__ x, const float* __restrict__ h,
    const float* __restrict__ w1,  const float* __restrict__ b1,
    const float* __restrict__ w12, const float* __restrict__ b12,
    const float* __restrict__ w13, const float* __restrict__ b13,
    const float* __restrict__ w14, const float* __restrict__ b14,
    const float* __restrict__ w15, const float* __restrict__ b15,
    const float* __restrict__ w2,  const float* __restrict__ b2,
    float* __restrict__ out)
{
    extern __shared__ u32 sm[];
    float* smf = (float*)sm;
    u16* smh = (u16*)sm;
    const int tid = threadIdx.x, lane = tid & 31, warp = tid >> 5;
    const int qr = lane >> 2, qc = lane & 3;

    // zero weights + biases (pads must be 0)
    for (int i = tid; i < A_OFS; i += TPB) sm[i] = 0u;
    __syncthreads();
    for (int i = tid; i < 20000; i += TPB) {              // w1 [100][200]
        int n = i / 200, k = i % 200;
        smh[(W1_OFS + n * 108) * 2 + k] = __half_as_ushort(__float2half_rn(w1[i]));
    }
    for (int i = tid; i < 5000; i += TPB) {               // w12 [50][100]
        int n = i / 100, k = i % 100;
        smh[(W12_OFS + n * 60) * 2 + k] = __half_as_ushort(__float2half_rn(w12[i]));
    }
    for (int i = tid; i < 4500; i += TPB) {               // w13 [30][150]
        int n = i / 150, k = i % 150;
        int kk = (k < 50) ? k : 64 + (k - 50);
        smh[(W13_OFS + n * 92) * 2 + kk] = __half_as_ushort(__float2half_rn(w13[i]));
    }
    for (int i = tid; i < 600; i += TPB) {                // w14 [20][30]
        int n = i / 30, k = i % 30;
        smh[(W14_OFS + n * 20) * 2 + k] = __half_as_ushort(__float2half_rn(w14[i]));
    }
    for (int i = tid; i < 4800; i += TPB) {               // w15 [40][120]
        int n = i / 120, k = i % 120;
        int kk = (k < 20) ? k : 32 + (k - 20);
        smh[(W15_OFS + n * 76) * 2 + kk] = __half_as_ushort(__float2half_rn(w15[i]));
    }
    for (int i = tid; i < 4000; i += TPB) {               // w2 [100][40]
        int n = i / 40, k = i % 40;
        smh[(W2_OFS + n * 28) * 2 + k] = __half_as_ushort(__float2half_rn(w2[i]));
    }
    for (int i = tid; i < 100; i += TPB) smf[B1_OFS + i] = b1[i];
    for (int i = tid; i < 50;  i += TPB) smf[B12_OFS + i] = b12[i];
    for (int i = tid; i < 30;  i += TPB) smf[B13_OFS + i] = b13[i];
    for (int i = tid; i < 20;  i += TPB) smf[B14_OFS + i] = b14[i];
    for (int i = tid; i < 40;  i += TPB) smf[B15_OFS + i] = b15[i];
    for (int i = tid; i < 100; i += TPB) smf[B2_OFS + i] = b2[i];
    __syncthreads();

    float p0 = 0.0f;

    for (int tile = blockIdx.x; tile < N_TILES; tile += PGRID) {
        const size_t r0 = (size_t)tile * TILE_M;
        // ---- stage A = [x|h] fp16 (zero tail rows + pads) ----
        for (int i = tid; i < TILE_M * 54; i += TPB) {
            int r = i / 54, u = i % 54;
            u32* dst = sm + A_OFS + r * 108;
            size_t gr = r0 + r;
            if (u < 25) {
                float4 v = make_float4(0.f, 0.f, 0.f, 0.f);
                if (gr < N_ROWS) v = *(const float4*)(x + gr * 100 + u * 4);
                dst[2 * u]     = pack_h2(v.x, v.y);
                dst[2 * u + 1] = pack_h2(v.z, v.w);
            } else if (u < 50) {
                int g = u - 25;
                float4 v = make_float4(0.f, 0.f, 0.f, 0.f);
                if (gr < N_ROWS) v = *(const float4*)(h + gr * 100 + g * 4);
                dst[50 + 2 * g]     = pack_h2(v.x, v.y);
                dst[50 + 2 * g + 1] = pack_h2(v.z, v.w);
            } else {
                dst[100 + 2 * (u - 50)]     = 0u;
                dst[100 + 2 * (u - 50) + 1] = 0u;
            }
        }
        __syncthreads();
        // L1: [x|h] -> z1 (N=112), 13 steps
        run_layer(sm, smf, warp, lane, W1_OFS, 108, B1_OFS,
                  A_OFS, 108, 13, 0, 0, 0, 0, Z1_OFS, 60, 7);
        __syncthreads();
        // L2: z1 -> z2 (N=64), 7 steps
        run_layer(sm, smf, warp, lane, W12_OFS, 60, B12_OFS,
                  Z1_OFS, 60, 7, 0, 0, 0, 0, Z2_OFS, 36, 4);
        __syncthreads();
        // L3: [z2|h] -> z3 (N=32), 4 + 7 steps (h at A+50, W k0w=32)
        run_layer(sm, smf, warp, lane, W13_OFS, 92, B13_OFS,
                  Z2_OFS, 36, 4, A_OFS + 50, 108, 7, 32, Z3_OFS, 20, 2);
        __syncthreads();
        // L4: z3 -> z4 (N=32), 2 steps
        run_layer(sm, smf, warp, lane, W14_OFS, 20, B14_OFS,
                  Z3_OFS, 20, 2, 0, 0, 0, 0, Z4_OFS, 20, 2);
        __syncthreads();
        // L5: [z4|h] -> z5 (N=48), 2 + 7 steps (W k0w=16)
        run_layer(sm, smf, warp, lane, W15_OFS, 76, B15_OFS,
                  Z4_OFS, 20, 2, A_OFS + 50, 108, 7, 16, Z5_OFS, 28, 3);
        __syncthreads();
        // L6: z5 -> f (N=112, fp32, no relu): direct store + fused part0
        for (int b = warp; b < 56; b += NWARP) {
            int rb = (b & 7) * 16, cb = (b >> 3) * 16;
            float c0[2][4] = {}, c1[2][4] = {};
            mma_seg(c0, c1, sm + W2_OFS, 28, sm + Z5_OFS, 28, 3, 0,
                    rb, cb, qr, qc);
            #pragma unroll
            for (int ni = 0; ni < 2; ni++) {
                int col = cb + ni * 8 + 2 * qc;
                if (col >= 100) continue;
                float b0v = smf[B2_OFS + col], b1v = smf[B2_OFS + col + 1];
                #pragma unroll
                for (int hh = 0; hh < 2; hh++) {
                    size_t grow = r0 + rb + qr + hh * 8;
                    float v0 = c0[ni][2 * hh]     + c1[ni][2 * hh]     + b0v;
                    float v1 = c0[ni][2 * hh + 1] + c1[ni][2 * hh + 1] + b1v;
                    if (grow < N_ROWS) {
                        *(float2*)(out + grow * 100 + col) = make_float2(v0, v1);
                        if (grow + 1 < N_ROWS) {
                            float2 xn = *(const float2*)(x + (grow + 1) * 100 + col);
                            float d0 = v0 - xn.x, d1 = v1 - xn.y;
                            p0 += d0 * d0 + d1 * d1;
                        }
                    }
                }
            }
        }
        __syncthreads();   // A/z tiles must drain before next staging
    }

    // block reduction of part0
    #pragma unroll
    for (int o = 16; o > 0; o >>= 1) p0 += __shfl_down_sync(0xffffffffu, p0, o);
    __shared__ float red[NWARP];
    if (lane == 0) red[warp] = p0;
    __syncthreads();
    if (tid == 0) {
        float acc = 0.0f;
        #pragma unroll
        for (int i = 0; i < NWARP; i++) acc += red[i];
        atomicAdd(&g_p0, (double)acc);
    }
}

// ---------------- h statistics ----------------
#define HS_ROWS 512
__global__ void h_stats(const float* __restrict__ h) {
    const int col = threadIdx.x;
    const long long r0 = (long long)blockIdx.x * HS_ROWS;
    long long r1 = r0 + HS_ROWS; if (r1 > N_ROWS) r1 = N_ROWS;

    float csum = 0.0f, sq = 0.0f, dif = 0.0f;
    if (col < 100 && r0 < N_ROWS) {
        float prev = h[r0 * 100 + col];
        csum = prev; sq = prev * prev;
        #pragma unroll 8
        for (long long r = r0 + 1; r < r1; ++r) {
            float v = h[r * 100 + col];
            csum += v;
            sq = fmaf(v, v, sq);
            dif += fabsf(v - prev);
            prev = v;
        }
        if (r1 < N_ROWS) dif += fabsf(h[r1 * 100 + col] - prev);
        atomicAdd(&g_mu[col], (double)csum);
    }
    __shared__ float ssq[128], sdf[128];
    ssq[threadIdx.x] = sq; sdf[threadIdx.x] = dif;
    __syncthreads();
    for (int off = 64; off > 0; off >>= 1) {
        if (threadIdx.x < off) {
            ssq[threadIdx.x] += ssq[threadIdx.x + off];
            sdf[threadIdx.x] += sdf[threadIdx.x + off];
        }
        __syncthreads();
    }
    if (threadIdx.x == 0) {
        atomicAdd(&g_sq, (double)ssq[0]);
        atomicAdd(&g_diff, (double)sdf[0]);
    }
}

// ---------------- finalize ----------------
__global__ void finalize(float* __restrict__ out) {
    __shared__ double smd[128];
    const int t = threadIdx.x;
    smd[t] = (t < 100) ? fabs(g_mu[t] / (double)N_ROWS) : 0.0;
    __syncthreads();
    for (int off = 64; off > 0; off >>= 1) {
        if (t < off) smd[t] += smd[t + off];
        __syncthreads();
    }
    if (t == 0) {
        out[OUT_SCALAR + 0] = (float)(sqrt(g_p0) / (double)(N_ROWS - 1));
        out[OUT_SCALAR + 1] = (float)(smd[0] / 100.0);
        out[OUT_SCALAR + 2] = (float)fabs(g_sq / (double)N_ROWS / 100.0 - 1.0);
        out[OUT_SCALAR + 3] = (float)(g_diff / (double)(N_ROWS - 1) / 100.0);
    }
}

// ---------------- launch ----------------
extern "C" void kernel_launch(void* const* d_in, const int* in_sizes, int n_in,
                              void* d_out, int out_size) {
    const float* x   = (const float*)d_in[0];
    const float* h   = (const float*)d_in[1];
    const float* w1  = (const float*)d_in[2];
    const float* b1  = (const float*)d_in[3];
    const float* w12 = (const float*)d_in[4];
    const float* b12 = (const float*)d_in[5];
    const float* w13 = (const float*)d_in[6];
    const float* b13 = (const float*)d_in[7];
    const float* w14 = (const float*)d_in[8];
    const float* b14 = (const float*)d_in[9];
    const float* w15 = (const float*)d_in[10];
    const float* b15 = (const float*)d_in[11];
    const float* w2  = (const float*)d_in[12];
    const float* b2  = (const float*)d_in[13];
    float* out = (float*)d_out;

    (void)in_sizes; (void)n_in; (void)out_size;

    cudaFuncSetAttribute(fused, cudaFuncAttributeMaxDynamicSharedMemorySize, SMEM_B);

    init_kernel<<<1, 128>>>();
    fused<<<PGRID, TPB, SMEM_B>>>(x, h, w1, b1, w12, b12, w13, b13,
                                  w14, b14, w15, b15, w2, b2, out);
    h_stats<<<(N_ROWS + HS_ROWS - 1) / HS_ROWS, 128>>>(h);
    finalize<<<1, 128>>>(out);
}

// round 13
// speedup vs baseline: 2.6053x; 1.0155x over previous
#include <cuda_runtime.h>
#include <cuda_fp16.h>
#include <math.h>

#define N_ROWS 500000
#define TILE_M 128
#define N_TILES ((N_ROWS + TILE_M - 1) / TILE_M)   // 3907
#define TPB 512
#define NWARP 16
#define PGRID 148

typedef unsigned int u32;
typedef unsigned short u16;

#define OUT_SCALAR ((size_t)N_ROWS * 100)

// ---------------- global accumulators ----------------
__device__ double g_p0;
__device__ double g_sq;
__device__ double g_diff;
__device__ double g_mu[100];

__global__ void init_kernel() {
    int t = threadIdx.x;
    if (t == 0) { g_p0 = 0.0; g_sq = 0.0; g_diff = 0.0; }
    if (t < 100) g_mu[t] = 0.0;
}

// ---------------- fp16 / mma / ldmatrix helpers ----------------
__device__ __forceinline__ u32 pack_h2(float a, float b) {
    __half2 t = __floats2half2_rn(a, b);
    return *reinterpret_cast<u32*>(&t);
}
__device__ __forceinline__ void mma16(float* d, u32 a0, u32 a1, u32 a2, u32 a3,
                                      u32 b0, u32 b1) {
    asm("mma.sync.aligned.m16n8k16.row.col.f32.f16.f16.f32 "
        "{%0,%1,%2,%3}, {%4,%5,%6,%7}, {%8,%9}, {%0,%1,%2,%3};"
        : "+f"(d[0]), "+f"(d[1]), "+f"(d[2]), "+f"(d[3])
        : "r"(a0), "r"(a1), "r"(a2), "r"(a3), "r"(b0), "r"(b1));
}
__device__ __forceinline__ void ldsm4(u32& r0, u32& r1, u32& r2, u32& r3, u32 addr) {
    asm volatile("ldmatrix.sync.aligned.m8n8.x4.shared.b16 {%0,%1,%2,%3}, [%4];"
        : "=r"(r0), "=r"(r1), "=r"(r2), "=r"(r3) : "r"(addr));
}
// lane address for a 16-row x 16-fp16 fragment (A or B identically):
// rows rowb+0..15 (lane&15), +16B for the k8..15 half (lane>>4).
// REQUIRES: stride_w % 4 == 0 and k0w % 4 == 0 (16B alignment for LDSM).
__device__ __forceinline__ u32 frag_addr(u32 base_b, int rowb, int stride_w,
                                         int k0w, int lane) {
    int l = lane & 15, hi = lane >> 4;
    return base_b + (u32)(((rowb + l) * stride_w + k0w) * 4 + hi * 16);
}

// 32r x 16c block k-segment: 2 A frags + 1 B frag per step, 8 mma.
__device__ __forceinline__ void mma_b32(float c[2][2][4], u32 aaddr, u32 a16,
                                        u32 baddr, int nsteps) {
    for (int s = 0; s < nsteps; s++) {
        u32 a0, a1, a2, a3, a4, a5, a6, a7, b0, b1, b2, b3;
        ldsm4(a0, a1, a2, a3, aaddr);
        ldsm4(a4, a5, a6, a7, aaddr + a16);
        ldsm4(b0, b1, b2, b3, baddr);
        mma16(c[0][0], a0, a1, a2, a3, b0, b2);
        mma16(c[0][1], a0, a1, a2, a3, b1, b3);
        mma16(c[1][0], a4, a5, a6, a7, b0, b2);
        mma16(c[1][1], a4, a5, a6, a7, b1, b3);
        aaddr += 32; baddr += 32;
    }
}
// 16r x 16c block k-segment: 1 A frag + 1 B frag, 4 mma.
__device__ __forceinline__ void mma_b16(float c[2][4], u32 aaddr, u32 baddr,
                                        int nsteps) {
    for (int s = 0; s < nsteps; s++) {
        u32 a0, a1, a2, a3, b0, b1, b2, b3;
        ldsm4(a0, a1, a2, a3, aaddr);
        ldsm4(b0, b1, b2, b3, baddr);
        mma16(c[0], a0, a1, a2, a3, b0, b2);
        mma16(c[1], a0, a1, a2, a3, b1, b3);
        aaddr += 32; baddr += 32;
    }
}

// ---------------- smem layout (u32 words) ----------------
// A/W1 k-space: [x: fp16 0-99 | pad 100-103 | h: 104-203 | pad 204-215]
// h starts at word 52 (208B, 16B-aligned for LDSM).
#define W1_OFS   0        // 112n x 108w
#define W12_OFS  12096    // 64n x 60w   (k: z1 0-111)
#define W13_OFS  15936    // 32n x 92w   (k: z2 0-63 | h 64-163 | pad)
#define W14_OFS  18880    // 32n x 20w   (k: z3 0-31)
#define W15_OFS  19520    // 48n x 76w   (k: z4 0-31 | h 32-143)
#define W2_OFS   23168    // 112n x 28w  (k: z5 0-47)
#define B1_OFS   26304    // fp32 112
#define B12_OFS  26416    // 64
#define B13_OFS  26480    // 32
#define B14_OFS  26512    // 32
#define B15_OFS  26544    // 48
#define B2_OFS   26592    // 112
#define A_OFS    26704    // 128r x 108w
#define Z1_OFS   40528    // 128r x 60w  (N=112)
#define Z3_OFS   40528    // reuse z1
#define Z4_OFS   43088    // reuse z1
#define Z2_OFS   48208    // 128r x 36w  (N=64)
#define Z5_OFS   52816    // 128r x 28w  (N=48)
#define SM_WORDS 56400
#define SMEM_B   (SM_WORDS * 4)   // 225,600 B

// 32x16-block layer (hidden: bias+relu -> fp16)
__device__ __forceinline__ void layer32(
    u32 sb, u32* sm, float* smf, int warp, int lane,
    int wofs, int ws, int bofs,
    int a0ofs, int as0, int ks0,
    int a1ofs, int as1, int ks1, int k0w1,
    int oofs, int os, int NT)
{
    const int qr = lane >> 2, qc = lane & 3;
    const float* bias = smf + bofs;
    for (int b = warp; b < 4 * NT; b += NWARP) {
        int rb = (b & 3) * 32, cb = (b >> 2) * 16;
        float c[2][2][4] = {};
        mma_b32(c, frag_addr(sb + a0ofs * 4, rb, as0, 0, lane), (u32)(16 * as0 * 4),
                frag_addr(sb + wofs * 4, cb, ws, 0, lane), ks0);
        if (ks1 > 0)
            mma_b32(c, frag_addr(sb + a1ofs * 4, rb, as1, 0, lane), (u32)(16 * as1 * 4),
                    frag_addr(sb + wofs * 4, cb, ws, k0w1, lane), ks1);
        #pragma unroll
        for (int mi = 0; mi < 2; mi++)
        #pragma unroll
        for (int ni = 0; ni < 2; ni++) {
            int col = cb + ni * 8 + 2 * qc;
            float b0v = bias[col], b1v = bias[col + 1];
            int r = rb + mi * 16 + qr;
            float v0 = fmaxf(c[mi][ni][0] + b0v, 0.0f);
            float v1 = fmaxf(c[mi][ni][1] + b1v, 0.0f);
            float v2 = fmaxf(c[mi][ni][2] + b0v, 0.0f);
            float v3 = fmaxf(c[mi][ni][3] + b1v, 0.0f);
            sm[oofs + (size_t)r * os + (col >> 1)]       = pack_h2(v0, v1);
            sm[oofs + (size_t)(r + 8) * os + (col >> 1)] = pack_h2(v2, v3);
        }
    }
}

// 16x16-block layer (for N=32 layers: keeps all 16 warps busy)
__device__ __forceinline__ void layer16(
    u32 sb, u32* sm, float* smf, int warp, int lane,
    int wofs, int ws, int bofs,
    int a0ofs, int as0, int ks0,
    int a1ofs, int as1, int ks1, int k0w1,
    int oofs, int os, int NT)
{
    const int qr = lane >> 2, qc = lane & 3;
    const float* bias = smf + bofs;
    for (int b = warp; b < 8 * NT; b += NWARP) {
        int rb = (b & 7) * 16, cb = (b >> 3) * 16;
        float c[2][4] = {};
        mma_b16(c, frag_addr(sb + a0ofs * 4, rb, as0, 0, lane),
                frag_addr(sb + wofs * 4, cb, ws, 0, lane), ks0);
        if (ks1 > 0)
            mma_b16(c, frag_addr(sb + a1ofs * 4, rb, as1, 0, lane),
                    frag_addr(sb + wofs * 4, cb, ws, k0w1, lane), ks1);
        #pragma unroll
        for (int ni = 0; ni < 2; ni++) {
            int col = cb + ni * 8 + 2 * qc;
            float b0v = bias[col], b1v = bias[col + 1];
            float v0 = fmaxf(c[ni][0] + b0v, 0.0f);
            float v1 = fmaxf(c[ni][1] + b1v, 0.0f);
            float v2 = fmaxf(c[ni][2] + b0v, 0.0f);
            float v3 = fmaxf(c[ni][3] + b1v, 0.0f);
            sm[oofs + (size_t)(rb + qr) * os + (col >> 1)]     = pack_h2(v0, v1);
            sm[oofs + (size_t)(rb + qr + 8) * os + (col >> 1)] = pack_h2(v2, v3);
        }
    }
}

// ================= fused MLP: all 6 layers, persistent =================
__global__ void __launch_bounds__(TPB, 1) fused(
    const float* __restrict__ x, const float* __restrict__ h,
    const float* __restrict__ w1,  const float* __restrict__ b1,
    const float* __restrict__ w12, const float* __restrict__ b12,
    const float* __restrict__ w13, const float* __restrict__ b13,
    const float* __restrict__ w14, const float* __restrict__ b14,
    const float* __restrict__ w15, const float* __restrict__ b15,
    const float* __restrict__ w2,  const float* __restrict__ b2,
    float* __restrict__ out)
{
    extern __shared__ u32 sm[];
    float* smf = (float*)sm;
    u16* smh = (u16*)sm;
    const u32 sb = (u32)__cvta_generic_to_shared(sm);
    const int tid = threadIdx.x, lane = tid & 31, warp = tid >> 5;
    const int qr = lane >> 2, qc = lane & 3;

    // zero weights + biases (pads must be 0)
    for (int i = tid; i < A_OFS; i += TPB) sm[i] = 0u;
    __syncthreads();
    for (int i = tid; i < 20000; i += TPB) {              // w1 [100][200]
        int n = i / 200, k = i % 200;
        int kk = (k < 100) ? k : k + 4;                   // h at fp16 slot 104
        smh[(W1_OFS + n * 108) * 2 + kk] = __half_as_ushort(__float2half_rn(w1[i]));
    }
    for (int i = tid; i < 5000; i += TPB) {               // w12 [50][100]
        int n = i / 100, k = i % 100;
        smh[(W12_OFS + n * 60) * 2 + k] = __half_as_ushort(__float2half_rn(w12[i]));
    }
    for (int i = tid; i < 4500; i += TPB) {               // w13 [30][150]
        int n = i / 150, k = i % 150;
        int kk = (k < 50) ? k : 64 + (k - 50);
        smh[(W13_OFS + n * 92) * 2 + kk] = __half_as_ushort(__float2half_rn(w13[i]));
    }
    for (int i = tid; i < 600; i += TPB) {                // w14 [20][30]
        int n = i / 30, k = i % 30;
        smh[(W14_OFS + n * 20) * 2 + k] = __half_as_ushort(__float2half_rn(w14[i]));
    }
    for (int i = tid; i < 4800; i += TPB) {               // w15 [40][120]
        int n = i / 120, k = i % 120;
        int kk = (k < 20) ? k : 32 + (k - 20);
        smh[(W15_OFS + n * 76) * 2 + kk] = __half_as_ushort(__float2half_rn(w15[i]));
    }
    for (int i = tid; i < 4000; i += TPB) {               // w2 [100][40]
        int n = i / 40, k = i % 40;
        smh[(W2_OFS + n * 28) * 2 + k] = __half_as_ushort(__float2half_rn(w2[i]));
    }
    for (int i = tid; i < 100; i += TPB) smf[B1_OFS + i] = b1[i];
    for (int i = tid; i < 50;  i += TPB) smf[B12_OFS + i] = b12[i];
    for (int i = tid; i < 30;  i += TPB) smf[B13_OFS + i] = b13[i];
    for (int i = tid; i < 20;  i += TPB) smf[B14_OFS + i] = b14[i];
    for (int i = tid; i < 40;  i += TPB) smf[B15_OFS + i] = b15[i];
    for (int i = tid; i < 100; i += TPB) smf[B2_OFS + i] = b2[i];
    __syncthreads();

    float p0 = 0.0f;

    for (int tile = blockIdx.x; tile < N_TILES; tile += PGRID) {
        const size_t r0 = (size_t)tile * TILE_M;
        // ---- stage A: x words 0-49 | zero 50-51 | h words 52-101 | zero 102-107
        for (int i = tid; i < TILE_M * 54; i += TPB) {
            int r = i / 54, u = i % 54;
            u32* dst = sm + A_OFS + r * 108;
            size_t gr = r0 + r;
            if (u < 25) {
                float4 v = make_float4(0.f, 0.f, 0.f, 0.f);
                if (gr < N_ROWS) v = *(const float4*)(x + gr * 100 + u * 4);
                dst[2 * u]     = pack_h2(v.x, v.y);
                dst[2 * u + 1] = pack_h2(v.z, v.w);
            } else if (u == 25) {
                dst[50] = 0u; dst[51] = 0u;
            } else if (u < 51) {
                int g = u - 26;
                float4 v = make_float4(0.f, 0.f, 0.f, 0.f);
                if (gr < N_ROWS) v = *(const float4*)(h + gr * 100 + g * 4);
                dst[52 + 2 * g] = pack_h2(v.x, v.y);
                dst[53 + 2 * g] = pack_h2(v.z, v.w);
            } else {
                dst[102 + 2 * (u - 51)]     = 0u;
                dst[103 + 2 * (u - 51)]     = 0u;
            }
        }
        __syncthreads();
        // L1: [x|h] -> z1 (N=112), 13 steps (k-space 208 fp16 incl. aligned pads)
        layer32(sb, sm, smf, warp, lane, W1_OFS, 108, B1_OFS,
                A_OFS, 108, 13, 0, 0, 0, 0, Z1_OFS, 60, 7);
        __syncthreads();
        // L2: z1 -> z2 (N=64), 7 steps
        layer32(sb, sm, smf, warp, lane, W12_OFS, 60, B12_OFS,
                Z1_OFS, 60, 7, 0, 0, 0, 0, Z2_OFS, 36, 4);
        __syncthreads();
        // L3: [z2|h] -> z3 (N=32), 4 + 7 steps (h at A+52w, W k0w=32w)
        layer16(sb, sm, smf, warp, lane, W13_OFS, 92, B13_OFS,
                Z2_OFS, 36, 4, A_OFS + 52, 108, 7, 32, Z3_OFS, 20, 2);
        __syncthreads();
        // L4: z3 -> z4 (N=32), 2 steps
        layer16(sb, sm, smf, warp, lane, W14_OFS, 20, B14_OFS,
                Z3_OFS, 20, 2, 0, 0, 0, 0, Z4_OFS, 20, 2);
        __syncthreads();
        // L5: [z4|h] -> z5 (N=48), 2 + 7 steps (h at A+52w, W k0w=16w)
        layer32(sb, sm, smf, warp, lane, W15_OFS, 76, B15_OFS,
                Z4_OFS, 20, 2, A_OFS + 52, 108, 7, 16, Z5_OFS, 28, 3);
        __syncthreads();
        // L6: z5 -> f (N=112, fp32, no relu): direct store + fused part0
        for (int b = warp; b < 28; b += NWARP) {
            int rb = (b & 3) * 32, cb = (b >> 2) * 16;
            float c[2][2][4] = {};
            mma_b32(c, frag_addr(sb + Z5_OFS * 4, rb, 28, 0, lane), (u32)(16 * 28 * 4),
                    frag_addr(sb + W2_OFS * 4, cb, 28, 0, lane), 3);
            #pragma unroll
            for (int mi = 0; mi < 2; mi++)
            #pragma unroll
            for (int ni = 0; ni < 2; ni++) {
                int col = cb + ni * 8 + 2 * qc;
                if (col >= 100) continue;
                float b0v = smf[B2_OFS + col], b1v = smf[B2_OFS + col + 1];
                #pragma unroll
                for (int hh = 0; hh < 2; hh++) {
                    size_t grow = r0 + rb + mi * 16 + qr + hh * 8;
                    float v0 = c[mi][ni][2 * hh]     + b0v;
                    float v1 = c[mi][ni][2 * hh + 1] + b1v;
                    if (grow < N_ROWS) {
                        *(float2*)(out + grow * 100 + col) = make_float2(v0, v1);
                        if (grow + 1 < N_ROWS) {
                            float2 xn = *(const float2*)(x + (grow + 1) * 100 + col);
                            float d0 = v0 - xn.x, d1 = v1 - xn.y;
                            p0 += d0 * d0 + d1 * d1;
                        }
                    }
                }
            }
        }
        __syncthreads();   // A/z tiles must drain before next staging
    }

    // block reduction of part0
    #pragma unroll
    for (int o = 16; o > 0; o >>= 1) p0 += __shfl_down_sync(0xffffffffu, p0, o);
    __shared__ float red[NWARP];
    if (lane == 0) red[warp] = p0;
    __syncthreads();
    if (tid == 0) {
        float acc = 0.0f;
        #pragma unroll
        for (int i = 0; i < NWARP; i++) acc += red[i];
        atomicAdd(&g_p0, (double)acc);
    }
}

// ---------------- h statistics ----------------
#define HS_ROWS 512
__global__ void h_stats(const float* __restrict__ h) {
    const int col = threadIdx.x;
    const long long r0 = (long long)blockIdx.x * HS_ROWS;
    long long r1 = r0 + HS_ROWS; if (r1 > N_ROWS) r1 = N_ROWS;

    float csum = 0.0f, sq = 0.0f, dif = 0.0f;
    if (col < 100 && r0 < N_ROWS) {
        float prev = h[r0 * 100 + col];
        csum = prev; sq = prev * prev;
        #pragma unroll 8
        for (long long r = r0 + 1; r < r1; ++r) {
            float v = h[r * 100 + col];
            csum += v;
            sq = fmaf(v, v, sq);
            dif += fabsf(v - prev);
            prev = v;
        }
        if (r1 < N_ROWS) dif += fabsf(h[r1 * 100 + col] - prev);
        atomicAdd(&g_mu[col], (double)csum);
    }
    __shared__ float ssq[128], sdf[128];
    ssq[threadIdx.x] = sq; sdf[threadIdx.x] = dif;
    __syncthreads();
    for (int off = 64; off > 0; off >>= 1) {
        if (threadIdx.x < off) {
            ssq[threadIdx.x] += ssq[threadIdx.x + off];
            sdf[threadIdx.x] += sdf[threadIdx.x + off];
        }
        __syncthreads();
    }
    if (threadIdx.x == 0) {
        atomicAdd(&g_sq, (double)ssq[0]);
        atomicAdd(&g_diff, (double)sdf[0]);
    }
}

// ---------------- finalize ----------------
__global__ void finalize(float* __restrict__ out) {
    __shared__ double smd[128];
    const int t = threadIdx.x;
    smd[t] = (t < 100) ? fabs(g_mu[t] / (double)N_ROWS) : 0.0;
    __syncthreads();
    for (int off = 64; off > 0; off >>= 1) {
        if (t < off) smd[t] += smd[t + off];
        __syncthreads();
    }
    if (t == 0) {
        out[OUT_SCALAR + 0] = (float)(sqrt(g_p0) / (double)(N_ROWS - 1));
        out[OUT_SCALAR + 1] = (float)(smd[0] / 100.0);
        out[OUT_SCALAR + 2] = (float)fabs(g_sq / (double)N_ROWS / 100.0 - 1.0);
        out[OUT_SCALAR + 3] = (float)(g_diff / (double)(N_ROWS - 1) / 100.0);
    }
}

// ---------------- launch ----------------
extern "C" void kernel_launch(void* const* d_in, const int* in_sizes, int n_in,
                              void* d_out, int out_size) {
    const float* x   = (const float*)d_in[0];
    const float* h   = (const float*)d_in[1];
    const float* w1  = (const float*)d_in[2];
    const float* b1  = (const float*)d_in[3];
    const float* w12 = (const float*)d_in[4];
    const float* b12 = (const float*)d_in[5];
    const float* w13 = (const float*)d_in[6];
    const float* b13 = (const float*)d_in[7];
    const float* w14 = (const float*)d_in[8];
    const float* b14 = (const float*)d_in[9];
    const float* w15 = (const float*)d_in[10];
    const float* b15 = (const float*)d_in[11];
    const float* w2  = (const float*)d_in[12];
    const float* b2  = (const float*)d_in[13];
    float* out = (float*)d_out;

    (void)in_sizes; (void)n_in; (void)out_size;

    cudaFuncSetAttribute(fused, cudaFuncAttributeMaxDynamicSharedMemorySize, SMEM_B);

    init_kernel<<<1, 128>>>();
    fused<<<PGRID, TPB, SMEM_B>>>(x, h, w1, b1, w12, b12, w13, b13,
                                  w14, b14, w15, b15, w2, b2, out);
    h_stats<<<(N_ROWS + HS_ROWS - 1) / HS_ROWS, 128>>>(h);
    finalize<<<1, 128>>>(out);
}

// round 15
// speedup vs baseline: 2.9307x; 1.1249x over previous
#include <cuda_runtime.h>
#include <cuda_fp16.h>
#include <math.h>

#define N_ROWS 500000
#define TILE_M 128
#define N_TILES ((N_ROWS + TILE_M - 1) / TILE_M)   // 3907
#define TPB 512
#define NWARP 16
#define PGRID 148

typedef unsigned int u32;
typedef unsigned short u16;

#define OUT_SCALAR ((size_t)N_ROWS * 100)

// ---------------- global accumulators ----------------
__device__ double g_p0;
__device__ double g_sq;
__device__ double g_diff;
__device__ double g_mu[100];

__global__ void init_kernel() {
    int t = threadIdx.x;
    if (t == 0) { g_p0 = 0.0; g_sq = 0.0; g_diff = 0.0; }
    if (t < 100) g_mu[t] = 0.0;
}

// ---------------- fp16 / mma / ldmatrix helpers ----------------
__device__ __forceinline__ u32 pack_h2(float a, float b) {
    __half2 t = __floats2half2_rn(a, b);
    return *reinterpret_cast<u32*>(&t);
}
__device__ __forceinline__ void mma16(float* d, u32 a0, u32 a1, u32 a2, u32 a3,
                                      u32 b0, u32 b1) {
    asm("mma.sync.aligned.m16n8k16.row.col.f32.f16.f16.f32 "
        "{%0,%1,%2,%3}, {%4,%5,%6,%7}, {%8,%9}, {%0,%1,%2,%3};"
        : "+f"(d[0]), "+f"(d[1]), "+f"(d[2]), "+f"(d[3])
        : "r"(a0), "r"(a1), "r"(a2), "r"(a3), "r"(b0), "r"(b1));
}
__device__ __forceinline__ void ldsm4(u32& r0, u32& r1, u32& r2, u32& r3, u32 addr) {
    asm volatile("ldmatrix.sync.aligned.m8n8.x4.shared.b16 {%0,%1,%2,%3}, [%4];"
        : "=r"(r0), "=r"(r1), "=r"(r2), "=r"(r3) : "r"(addr));
}
// group barrier: 128 threads, ids 1..4 (id 0 reserved for __syncthreads)
__device__ __forceinline__ void gbar(int id) {
    asm volatile("bar.sync %0, 128;" :: "r"(id) : "memory");
}
// lane address for a 16-row x 16-fp16 fragment; stride_w%4==0, k0w%4==0.
__device__ __forceinline__ u32 frag_addr(u32 base_b, int rowb, int stride_w,
                                         int k0w, int lane) {
    int l = lane & 15, hi = lane >> 4;
    return base_b + (u32)(((rowb + l) * stride_w + k0w) * 4 + hi * 16);
}

// 32r x 16c block k-segment: 2 A frags + 1 B frag per step, 8 mma.
__device__ __forceinline__ void mma_b32(float c[2][2][4], u32 aaddr, u32 a16,
                                        u32 baddr, int nsteps) {
    for (int s = 0; s < nsteps; s++) {
        u32 a0, a1, a2, a3, a4, a5, a6, a7, b0, b1, b2, b3;
        ldsm4(a0, a1, a2, a3, aaddr);
        ldsm4(a4, a5, a6, a7, aaddr + a16);
        ldsm4(b0, b1, b2, b3, baddr);
        mma16(c[0][0], a0, a1, a2, a3, b0, b2);
        mma16(c[0][1], a0, a1, a2, a3, b1, b3);
        mma16(c[1][0], a4, a5, a6, a7, b0, b2);
        mma16(c[1][1], a4, a5, a6, a7, b1, b3);
        aaddr += 32; baddr += 32;
    }
}
// 16r x 16c block k-segment
__device__ __forceinline__ void mma_b16(float c[2][4], u32 aaddr, u32 baddr,
                                        int nsteps) {
    for (int s = 0; s < nsteps; s++) {
        u32 a0, a1, a2, a3, b0, b1, b2, b3;
        ldsm4(a0, a1, a2, a3, aaddr);
        ldsm4(b0, b1, b2, b3, baddr);
        mma16(c[0], a0, a1, a2, a3, b0, b2);
        mma16(c[1], a0, a1, a2, a3, b1, b3);
        aaddr += 32; baddr += 32;
    }
}

// ---------------- smem layout (u32 words) ----------------
// A/W1 k-space: [x: fp16 0-99 | pad 100-103 | h: 104-203 | pad 204-215]
// z3/z4 reuse z1's ROWS (stride 60) so every buffer stays row-partitioned:
//   z3 row r = Z1_OFS + r*60 + 0  (20 words)
//   z4 row r = Z1_OFS + r*60 + 20 (20 words)
// -> no cross-group aliasing under group-local barriers.
#define W1_OFS   0        // 112n x 108w
#define W12_OFS  12096    // 64n x 60w
#define W13_OFS  15936    // 32n x 92w   (k: z2 0-63 | h 64-163)
#define W14_OFS  18880    // 32n x 20w
#define W15_OFS  19520    // 48n x 76w   (k: z4 0-31 | h 32-143)
#define W2_OFS   23168    // 112n x 28w
#define B1_OFS   26304
#define B12_OFS  26416
#define B13_OFS  26480
#define B14_OFS  26512
#define B15_OFS  26544
#define B2_OFS   26592
#define A_OFS    26704    // 128r x 108w
#define Z1_OFS   40528    // 128r x 60w
#define Z2_OFS   48208    // 128r x 36w
#define Z5_OFS   52816    // 128r x 28w
#define SM_WORDS 56400
#define SMEM_B   (SM_WORDS * 4)   // 225,600 B

// group-scoped 32x16-block layer (hidden: bias+relu -> fp16); rb0 = group row base
__device__ __forceinline__ void layer32g(
    u32 sb, u32* sm, float* smf, int wig, int lane, int rb0,
    int wofs, int ws, int bofs,
    int a0ofs, int as0, int ks0,
    int a1ofs, int as1, int ks1, int k0w1,
    int oofs, int os, int NT)
{
    const int qr = lane >> 2, qc = lane & 3;
    const float* bias = smf + bofs;
    for (int b = wig; b < NT; b += 4) {
        int cb = b * 16;
        float c[2][2][4] = {};
        mma_b32(c, frag_addr(sb + a0ofs * 4, rb0, as0, 0, lane), (u32)(16 * as0 * 4),
                frag_addr(sb + wofs * 4, cb, ws, 0, lane), ks0);
        if (ks1 > 0)
            mma_b32(c, frag_addr(sb + a1ofs * 4, rb0, as1, 0, lane), (u32)(16 * as1 * 4),
                    frag_addr(sb + wofs * 4, cb, ws, k0w1, lane), ks1);
        #pragma unroll
        for (int mi = 0; mi < 2; mi++)
        #pragma unroll
        for (int ni = 0; ni < 2; ni++) {
            int col = cb + ni * 8 + 2 * qc;
            float b0v = bias[col], b1v = bias[col + 1];
            int r = rb0 + mi * 16 + qr;
            float v0 = fmaxf(c[mi][ni][0] + b0v, 0.0f);
            float v1 = fmaxf(c[mi][ni][1] + b1v, 0.0f);
            float v2 = fmaxf(c[mi][ni][2] + b0v, 0.0f);
            float v3 = fmaxf(c[mi][ni][3] + b1v, 0.0f);
            sm[oofs + (size_t)r * os + (col >> 1)]       = pack_h2(v0, v1);
            sm[oofs + (size_t)(r + 8) * os + (col >> 1)] = pack_h2(v2, v3);
        }
    }
}

// group-scoped 16x16-block layer (N=32 layers: 2 row-blocks x NT2 col-blocks)
// NOTE: oofs may carry an intra-row word offset (z4); os is the row stride.
__device__ __forceinline__ void layer16g(
    u32 sb, u32* sm, float* smf, int wig, int lane, int rb0,
    int wofs, int ws, int bofs,
    int a0ofs, int as0, int ks0,
    int a1ofs, int as1, int ks1, int k0w1,
    int oofs, int os, int NT2)
{
    const int qr = lane >> 2, qc = lane & 3;
    const float* bias = smf + bofs;
    for (int b = wig; b < 2 * NT2; b += 4) {
        int rb = rb0 + (b & 1) * 16, cb = (b >> 1) * 16;
        float c[2][4] = {};
        mma_b16(c, frag_addr(sb + a0ofs * 4, rb, as0, 0, lane),
                frag_addr(sb + wofs * 4, cb, ws, 0, lane), ks0);
        if (ks1 > 0)
            mma_b16(c, frag_addr(sb + a1ofs * 4, rb, as1, 0, lane),
                    frag_addr(sb + wofs * 4, cb, ws, k0w1, lane), ks1);
        #pragma unroll
        for (int ni = 0; ni < 2; ni++) {
            int col = cb + ni * 8 + 2 * qc;
            float b0v = bias[col], b1v = bias[col + 1];
            float v0 = fmaxf(c[ni][0] + b0v, 0.0f);
            float v1 = fmaxf(c[ni][1] + b1v, 0.0f);
            float v2 = fmaxf(c[ni][2] + b0v, 0.0f);
            float v3 = fmaxf(c[ni][3] + b1v, 0.0f);
            sm[oofs + (size_t)(rb + qr) * os + (col >> 1)]     = pack_h2(v0, v1);
            sm[oofs + (size_t)(rb + qr + 8) * os + (col >> 1)] = pack_h2(v2, v3);
        }
    }
}

// ================= fused MLP: 4 independent row-groups per CTA =================
__global__ void __launch_bounds__(TPB, 1) fused(
    const float* __restrict__ x, const float* __restrict__ h,
    const float* __restrict__ w1,  const float* __restrict__ b1,
    const float* __restrict__ w12, const float* __restrict__ b12,
    const float* __restrict__ w13, const float* __restrict__ b13,
    const float* __restrict__ w14, const float* __restrict__ b14,
    const float* __restrict__ w15, const float* __restrict__ b15,
    const float* __restrict__ w2,  const float* __restrict__ b2,
    float* __restrict__ out)
{
    extern __shared__ u32 sm[];
    float* smf = (float*)sm;
    u16* smh = (u16*)sm;
    const u32 sb = (u32)__cvta_generic_to_shared(sm);
    const int tid = threadIdx.x, lane = tid & 31, warp = tid >> 5;
    const int qr = lane >> 2, qc = lane & 3;
    const int grp = tid >> 7;          // 0..3 (4 warps each)
    const int wig = warp & 3;          // warp within group
    const int ltid = tid & 127;        // thread within group
    const int bid = grp + 1;           // named barrier id
    const int rb0 = grp * 32;          // group's row quarter

    // ---- weights + biases (full CTA, once) ----
    for (int i = tid; i < A_OFS; i += TPB) sm[i] = 0u;
    __syncthreads();
    for (int i = tid; i < 20000; i += TPB) {              // w1 [100][200]
        int n = i / 200, k = i % 200;
        int kk = (k < 100) ? k : k + 4;                   // h at fp16 slot 104
        smh[(W1_OFS + n * 108) * 2 + kk] = __half_as_ushort(__float2half_rn(w1[i]));
    }
    for (int i = tid; i < 5000; i += TPB) {               // w12 [50][100]
        int n = i / 100, k = i % 100;
        smh[(W12_OFS + n * 60) * 2 + k] = __half_as_ushort(__float2half_rn(w12[i]));
    }
    for (int i = tid; i < 4500; i += TPB) {               // w13 [30][150]
        int n = i / 150, k = i % 150;
        int kk = (k < 50) ? k : 64 + (k - 50);
        smh[(W13_OFS + n * 92) * 2 + kk] = __half_as_ushort(__float2half_rn(w13[i]));
    }
    for (int i = tid; i < 600; i += TPB) {                // w14 [20][30]
        int n = i / 30, k = i % 30;
        smh[(W14_OFS + n * 20) * 2 + k] = __half_as_ushort(__float2half_rn(w14[i]));
    }
    for (int i = tid; i < 4800; i += TPB) {               // w15 [40][120]
        int n = i / 120, k = i % 120;
        int kk = (k < 20) ? k : 32 + (k - 20);
        smh[(W15_OFS + n * 76) * 2 + kk] = __half_as_ushort(__float2half_rn(w15[i]));
    }
    for (int i = tid; i < 4000; i += TPB) {               // w2 [100][40]
        int n = i / 40, k = i % 40;
        smh[(W2_OFS + n * 28) * 2 + k] = __half_as_ushort(__float2half_rn(w2[i]));
    }
    for (int i = tid; i < 100; i += TPB) smf[B1_OFS + i] = b1[i];
    for (int i = tid; i < 50;  i += TPB) smf[B12_OFS + i] = b12[i];
    for (int i = tid; i < 30;  i += TPB) smf[B13_OFS + i] = b13[i];
    for (int i = tid; i < 20;  i += TPB) smf[B14_OFS + i] = b14[i];
    for (int i = tid; i < 40;  i += TPB) smf[B15_OFS + i] = b15[i];
    for (int i = tid; i < 100; i += TPB) smf[B2_OFS + i] = b2[i];
    __syncthreads();

    float p0 = 0.0f;

    for (int tile = blockIdx.x; tile < N_TILES; tile += PGRID) {
        const size_t r0 = (size_t)tile * TILE_M;
        // ---- group-local staging of its 32 rows ----
        for (int i = ltid; i < 32 * 54; i += 128) {
            int r = rb0 + i / 54, u = i % 54;
            u32* dst = sm + A_OFS + r * 108;
            size_t gr = r0 + r;
            if (u < 25) {
                float4 v = make_float4(0.f, 0.f, 0.f, 0.f);
                if (gr < N_ROWS) v = *(const float4*)(x + gr * 100 + u * 4);
                dst[2 * u]     = pack_h2(v.x, v.y);
                dst[2 * u + 1] = pack_h2(v.z, v.w);
            } else if (u == 25) {
                dst[50] = 0u; dst[51] = 0u;
            } else if (u < 51) {
                int g = u - 26;
                float4 v = make_float4(0.f, 0.f, 0.f, 0.f);
                if (gr < N_ROWS) v = *(const float4*)(h + gr * 100 + g * 4);
                dst[52 + 2 * g] = pack_h2(v.x, v.y);
                dst[53 + 2 * g] = pack_h2(v.z, v.w);
            } else {
                dst[102 + 2 * (u - 51)] = 0u;
                dst[103 + 2 * (u - 51)] = 0u;
            }
        }
        gbar(bid);
        // L1: [x|h] -> z1 (N=112), 13 steps
        layer32g(sb, sm, smf, wig, lane, rb0, W1_OFS, 108, B1_OFS,
                 A_OFS, 108, 13, 0, 0, 0, 0, Z1_OFS, 60, 7);
        gbar(bid);
        // L2: z1 -> z2 (N=64), 7 steps
        layer32g(sb, sm, smf, wig, lane, rb0, W12_OFS, 60, B12_OFS,
                 Z1_OFS, 60, 7, 0, 0, 0, 0, Z2_OFS, 36, 4);
        gbar(bid);
        // L3: [z2|h] -> z3 (N=32), 4 + 7 steps; z3 row r = Z1 + r*60 (z1 dead)
        layer16g(sb, sm, smf, wig, lane, rb0, W13_OFS, 92, B13_OFS,
                 Z2_OFS, 36, 4, A_OFS + 52, 108, 7, 32, Z1_OFS, 60, 2);
        gbar(bid);
        // L4: z3 -> z4 (N=32), 2 steps; z4 row r = Z1 + r*60 + 20
        layer16g(sb, sm, smf, wig, lane, rb0, W14_OFS, 20, B14_OFS,
                 Z1_OFS, 60, 2, 0, 0, 0, 0, Z1_OFS + 20, 60, 2);
        gbar(bid);
        // L5: [z4|h] -> z5 (N=48), 2 + 7 steps; z4 at Z1+20, stride 60
        layer32g(sb, sm, smf, wig, lane, rb0, W15_OFS, 76, B15_OFS,
                 Z1_OFS + 20, 60, 2, A_OFS + 52, 108, 7, 16, Z5_OFS, 28, 3);
        gbar(bid);
        // L6: z5 -> f (N=112, fp32, no relu): direct store + fused part0
        for (int b = wig; b < 7; b += 4) {
            int cb = b * 16;
            float c[2][2][4] = {};
            mma_b32(c, frag_addr(sb + Z5_OFS * 4, rb0, 28, 0, lane), (u32)(16 * 28 * 4),
                    frag_addr(sb + W2_OFS * 4, cb, 28, 0, lane), 3);
            #pragma unroll
            for (int mi = 0; mi < 2; mi++)
            #pragma unroll
            for (int ni = 0; ni < 2; ni++) {
                int col = cb + ni * 8 + 2 * qc;
                if (col >= 100) continue;
                float b0v = smf[B2_OFS + col], b1v = smf[B2_OFS + col + 1];
                #pragma unroll
                for (int hh = 0; hh < 2; hh++) {
                    size_t grow = r0 + rb0 + mi * 16 + qr + hh * 8;
                    float v0 = c[mi][ni][2 * hh]     + b0v;
                    float v1 = c[mi][ni][2 * hh + 1] + b1v;
                    if (grow < N_ROWS) {
                        *(float2*)(out + grow * 100 + col) = make_float2(v0, v1);
                        if (grow + 1 < N_ROWS) {
                            float2 xn = *(const float2*)(x + (grow + 1) * 100 + col);
                            float d0 = v0 - xn.x, d1 = v1 - xn.y;
                            p0 += d0 * d0 + d1 * d1;
                        }
                    }
                }
            }
        }
        gbar(bid);   // group's Z5/A reads done before its next-tile staging
    }

    // ---- CTA-wide part0 reduction (only full sync point after weights) ----
    #pragma unroll
    for (int o = 16; o > 0; o >>= 1) p0 += __shfl_down_sync(0xffffffffu, p0, o);
    __shared__ float red[NWARP];
    if (lane == 0) red[warp] = p0;
    __syncthreads();
    if (tid == 0) {
        float acc = 0.0f;
        #pragma unroll
        for (int i = 0; i < NWARP; i++) acc += red[i];
        atomicAdd(&g_p0, (double)acc);
    }
}

// ---------------- h statistics ----------------
#define HS_ROWS 512
__global__ void h_stats(const float* __restrict__ h) {
    const int col = threadIdx.x;
    const long long r0 = (long long)blockIdx.x * HS_ROWS;
    long long r1 = r0 + HS_ROWS; if (r1 > N_ROWS) r1 = N_ROWS;

    float csum = 0.0f, sq = 0.0f, dif = 0.0f;
    if (col < 100 && r0 < N_ROWS) {
        float prev = h[r0 * 100 + col];
        csum = prev; sq = prev * prev;
        #pragma unroll 8
        for (long long r = r0 + 1; r < r1; ++r) {
            float v = h[r * 100 + col];
            csum += v;
            sq = fmaf(v, v, sq);
            dif += fabsf(v - prev);
            prev = v;
        }
        if (r1 < N_ROWS) dif += fabsf(h[r1 * 100 + col] - prev);
        atomicAdd(&g_mu[col], (double)csum);
    }
    __shared__ float ssq[128], sdf[128];
    ssq[threadIdx.x] = sq; sdf[threadIdx.x] = dif;
    __syncthreads();
    for (int off = 64; off > 0; off >>= 1) {
        if (threadIdx.x < off) {
            ssq[threadIdx.x] += ssq[threadIdx.x + off];
            sdf[threadIdx.x] += sdf[threadIdx.x + off];
        }
        __syncthreads();
    }
    if (threadIdx.x == 0) {
        atomicAdd(&g_sq, (double)ssq[0]);
        atomicAdd(&g_diff, (double)sdf[0]);
    }
}

// ---------------- finalize ----------------
__global__ void finalize(float* __restrict__ out) {
    __shared__ double smd[128];
    const int t = threadIdx.x;
    smd[t] = (t < 100) ? fabs(g_mu[t] / (double)N_ROWS) : 0.0;
    __syncthreads();
    for (int off = 64; off > 0; off >>= 1) {
        if (t < off) smd[t] += smd[t + off];
        __syncthreads();
    }
    if (t == 0) {
        out[OUT_SCALAR + 0] = (float)(sqrt(g_p0) / (double)(N_ROWS - 1));
        out[OUT_SCALAR + 1] = (float)(smd[0] / 100.0);
        out[OUT_SCALAR + 2] = (float)fabs(g_sq / (double)N_ROWS / 100.0 - 1.0);
        out[OUT_SCALAR + 3] = (float)(g_diff / (double)(N_ROWS - 1) / 100.0);
    }
}

// ---------------- launch ----------------
extern "C" void kernel_launch(void* const* d_in, const int* in_sizes, int n_in,
                              void* d_out, int out_size) {
    const float* x   = (const float*)d_in[0];
    const float* h   = (const float*)d_in[1];
    const float* w1  = (const float*)d_in[2];
    const float* b1  = (const float*)d_in[3];
    const float* w12 = (const float*)d_in[4];
    const float* b12 = (const float*)d_in[5];
    const float* w13 = (const float*)d_in[6];
    const float* b13 = (const float*)d_in[7];
    const float* w14 = (const float*)d_in[8];
    const float* b14 = (const float*)d_in[9];
    const float* w15 = (const float*)d_in[10];
    const float* b15 = (const float*)d_in[11];
    const float* w2  = (const float*)d_in[12];
    const float* b2  = (const float*)d_in[13];
    float* out = (float*)d_out;

    (void)in_sizes; (void)n_in; (void)out_size;

    cudaFuncSetAttribute(fused, cudaFuncAttributeMaxDynamicSharedMemorySize, SMEM_B);

    init_kernel<<<1, 128>>>();
    fused<<<PGRID, TPB, SMEM_B>>>(x, h, w1, b1, w12, b12, w13, b13,
                                  w14, b14, w15, b15, w2, b2, out);
    h_stats<<<(N_ROWS + HS_ROWS - 1) / HS_ROWS, 128>>>(h);
    finalize<<<1, 128>>>(out);
}

// round 16
// speedup vs baseline: 2.9382x; 1.0026x over previous
#include <cuda_runtime.h>
#include <cuda_fp16.h>
#include <math.h>

#define N_ROWS 500000
#define TILE_M 128
#define N_TILES ((N_ROWS + TILE_M - 1) / TILE_M)   // 3907
#define TPB 512
#define NWARP 16
#define PGRID 148

typedef unsigned int u32;
typedef unsigned short u16;

#define OUT_SCALAR ((size_t)N_ROWS * 100)

// ---------------- global accumulators ----------------
__device__ double g_p0;
__device__ double g_sq;
__device__ double g_diff;
__device__ double g_mu[100];

__global__ void init_kernel() {
    int t = threadIdx.x;
    if (t == 0) { g_p0 = 0.0; g_sq = 0.0; g_diff = 0.0; }
    if (t < 100) g_mu[t] = 0.0;
}

// ---------------- fp16 / mma / ldmatrix helpers ----------------
__device__ __forceinline__ u32 pack_h2(float a, float b) {
    __half2 t = __floats2half2_rn(a, b);
    return *reinterpret_cast<u32*>(&t);
}
__device__ __forceinline__ void mma16(float* d, u32 a0, u32 a1, u32 a2, u32 a3,
                                      u32 b0, u32 b1) {
    asm("mma.sync.aligned.m16n8k16.row.col.f32.f16.f16.f32 "
        "{%0,%1,%2,%3}, {%4,%5,%6,%7}, {%8,%9}, {%0,%1,%2,%3};"
        : "+f"(d[0]), "+f"(d[1]), "+f"(d[2]), "+f"(d[3])
        : "r"(a0), "r"(a1), "r"(a2), "r"(a3), "r"(b0), "r"(b1));
}
__device__ __forceinline__ void ldsm4(u32& r0, u32& r1, u32& r2, u32& r3, u32 addr) {
    asm volatile("ldmatrix.sync.aligned.m8n8.x4.shared.b16 {%0,%1,%2,%3}, [%4];"
        : "=r"(r0), "=r"(r1), "=r"(r2), "=r"(r3) : "r"(addr));
}
// group barrier: 128 threads, ids 1..4 (id 0 reserved for __syncthreads)
__device__ __forceinline__ void gbar(int id) {
    asm volatile("bar.sync %0, 128;" :: "r"(id) : "memory");
}
// lane address for a 16-row x 16-fp16 fragment; stride_w%4==0, k0w%4==0.
__device__ __forceinline__ u32 frag_addr(u32 base_b, int rowb, int stride_w,
                                         int k0w, int lane) {
    int l = lane & 15, hi = lane >> 4;
    return base_b + (u32)(((rowb + l) * stride_w + k0w) * 4 + hi * 16);
}

// 32r x 16c block k-segment, chain-split: even steps -> c, odd steps -> d.
// Both steps' fragments are loaded before the MMAs (overlaps LDSM latency).
__device__ __forceinline__ void mma_b32(float c[2][2][4], float d[2][2][4],
                                        u32 aaddr, u32 a16, u32 baddr, int nsteps) {
    int s = 0;
    for (; s + 1 < nsteps; s += 2) {
        u32 a0, a1, a2, a3, a4, a5, a6, a7, b0, b1, b2, b3;
        u32 e0, e1, e2, e3, e4, e5, e6, e7, f0, f1, f2, f3;
        ldsm4(a0, a1, a2, a3, aaddr);
        ldsm4(a4, a5, a6, a7, aaddr + a16);
        ldsm4(b0, b1, b2, b3, baddr);
        ldsm4(e0, e1, e2, e3, aaddr + 32);
        ldsm4(e4, e5, e6, e7, aaddr + a16 + 32);
        ldsm4(f0, f1, f2, f3, baddr + 32);
        mma16(c[0][0], a0, a1, a2, a3, b0, b2);
        mma16(c[0][1], a0, a1, a2, a3, b1, b3);
        mma16(c[1][0], a4, a5, a6, a7, b0, b2);
        mma16(c[1][1], a4, a5, a6, a7, b1, b3);
        mma16(d[0][0], e0, e1, e2, e3, f0, f2);
        mma16(d[0][1], e0, e1, e2, e3, f1, f3);
        mma16(d[1][0], e4, e5, e6, e7, f0, f2);
        mma16(d[1][1], e4, e5, e6, e7, f1, f3);
        aaddr += 64; baddr += 64;
    }
    if (s < nsteps) {
        u32 a0, a1, a2, a3, a4, a5, a6, a7, b0, b1, b2, b3;
        ldsm4(a0, a1, a2, a3, aaddr);
        ldsm4(a4, a5, a6, a7, aaddr + a16);
        ldsm4(b0, b1, b2, b3, baddr);
        mma16(c[0][0], a0, a1, a2, a3, b0, b2);
        mma16(c[0][1], a0, a1, a2, a3, b1, b3);
        mma16(c[1][0], a4, a5, a6, a7, b0, b2);
        mma16(c[1][1], a4, a5, a6, a7, b1, b3);
    }
}
// 16r x 16c block k-segment, chain-split identically.
__device__ __forceinline__ void mma_b16(float c[2][4], float d[2][4],
                                        u32 aaddr, u32 baddr, int nsteps) {
    int s = 0;
    for (; s + 1 < nsteps; s += 2) {
        u32 a0, a1, a2, a3, b0, b1, b2, b3;
        u32 e0, e1, e2, e3, f0, f1, f2, f3;
        ldsm4(a0, a1, a2, a3, aaddr);
        ldsm4(b0, b1, b2, b3, baddr);
        ldsm4(e0, e1, e2, e3, aaddr + 32);
        ldsm4(f0, f1, f2, f3, baddr + 32);
        mma16(c[0], a0, a1, a2, a3, b0, b2);
        mma16(c[1], a0, a1, a2, a3, b1, b3);
        mma16(d[0], e0, e1, e2, e3, f0, f2);
        mma16(d[1], e0, e1, e2, e3, f1, f3);
        aaddr += 64; baddr += 64;
    }
    if (s < nsteps) {
        u32 a0, a1, a2, a3, b0, b1, b2, b3;
        ldsm4(a0, a1, a2, a3, aaddr);
        ldsm4(b0, b1, b2, b3, baddr);
        mma16(c[0], a0, a1, a2, a3, b0, b2);
        mma16(c[1], a0, a1, a2, a3, b1, b3);
    }
}

// ---------------- smem layout (u32 words) — identical to R15 ----------------
// A/W1 k-space: [x: fp16 0-99 | pad 100-103 | h: 104-203 | pad 204-215]
// z3 row r = Z1_OFS + r*60 + 0 (20 words); z4 row r = Z1_OFS + r*60 + 20.
#define W1_OFS   0        // 112n x 108w
#define W12_OFS  12096    // 64n x 60w
#define W13_OFS  15936    // 32n x 92w   (k: z2 0-63 | h 64-163)
#define W14_OFS  18880    // 32n x 20w
#define W15_OFS  19520    // 48n x 76w   (k: z4 0-31 | h 32-143)
#define W2_OFS   23168    // 112n x 28w
#define B1_OFS   26304
#define B12_OFS  26416
#define B13_OFS  26480
#define B14_OFS  26512
#define B15_OFS  26544
#define B2_OFS   26592
#define A_OFS    26704    // 128r x 108w
#define Z1_OFS   40528    // 128r x 60w
#define Z2_OFS   48208    // 128r x 36w
#define Z5_OFS   52816    // 128r x 28w
#define SM_WORDS 56400
#define SMEM_B   (SM_WORDS * 4)   // 225,600 B

// group-scoped 32x16-block layer (hidden: bias+relu -> fp16); rb0 = group row base
__device__ __forceinline__ void layer32g(
    u32 sb, u32* sm, float* smf, int wig, int lane, int rb0,
    int wofs, int ws, int bofs,
    int a0ofs, int as0, int ks0,
    int a1ofs, int as1, int ks1, int k0w1,
    int oofs, int os, int NT)
{
    const int qr = lane >> 2, qc = lane & 3;
    const float* bias = smf + bofs;
    for (int b = wig; b < NT; b += 4) {
        int cb = b * 16;
        float c[2][2][4] = {}, d[2][2][4] = {};
        mma_b32(c, d, frag_addr(sb + a0ofs * 4, rb0, as0, 0, lane), (u32)(16 * as0 * 4),
                frag_addr(sb + wofs * 4, cb, ws, 0, lane), ks0);
        if (ks1 > 0)
            mma_b32(c, d, frag_addr(sb + a1ofs * 4, rb0, as1, 0, lane), (u32)(16 * as1 * 4),
                    frag_addr(sb + wofs * 4, cb, ws, k0w1, lane), ks1);
        #pragma unroll
        for (int mi = 0; mi < 2; mi++)
        #pragma unroll
        for (int ni = 0; ni < 2; ni++) {
            int col = cb + ni * 8 + 2 * qc;
            float b0v = bias[col], b1v = bias[col + 1];
            int r = rb0 + mi * 16 + qr;
            float v0 = fmaxf(c[mi][ni][0] + d[mi][ni][0] + b0v, 0.0f);
            float v1 = fmaxf(c[mi][ni][1] + d[mi][ni][1] + b1v, 0.0f);
            float v2 = fmaxf(c[mi][ni][2] + d[mi][ni][2] + b0v, 0.0f);
            float v3 = fmaxf(c[mi][ni][3] + d[mi][ni][3] + b1v, 0.0f);
            sm[oofs + (size_t)r * os + (col >> 1)]       = pack_h2(v0, v1);
            sm[oofs + (size_t)(r + 8) * os + (col >> 1)] = pack_h2(v2, v3);
        }
    }
}

// group-scoped 16x16-block layer (N=32 layers); oofs may carry intra-row offset.
__device__ __forceinline__ void layer16g(
    u32 sb, u32* sm, float* smf, int wig, int lane, int rb0,
    int wofs, int ws, int bofs,
    int a0ofs, int as0, int ks0,
    int a1ofs, int as1, int ks1, int k0w1,
    int oofs, int os, int NT2)
{
    const int qr = lane >> 2, qc = lane & 3;
    const float* bias = smf + bofs;
    for (int b = wig; b < 2 * NT2; b += 4) {
        int rb = rb0 + (b & 1) * 16, cb = (b >> 1) * 16;
        float c[2][4] = {}, d[2][4] = {};
        mma_b16(c, d, frag_addr(sb + a0ofs * 4, rb, as0, 0, lane),
                frag_addr(sb + wofs * 4, cb, ws, 0, lane), ks0);
        if (ks1 > 0)
            mma_b16(c, d, frag_addr(sb + a1ofs * 4, rb, as1, 0, lane),
                    frag_addr(sb + wofs * 4, cb, ws, k0w1, lane), ks1);
        #pragma unroll
        for (int ni = 0; ni < 2; ni++) {
            int col = cb + ni * 8 + 2 * qc;
            float b0v = bias[col], b1v = bias[col + 1];
            float v0 = fmaxf(c[ni][0] + d[ni][0] + b0v, 0.0f);
            float v1 = fmaxf(c[ni][1] + d[ni][1] + b1v, 0.0f);
            float v2 = fmaxf(c[ni][2] + d[ni][2] + b0v, 0.0f);
            float v3 = fmaxf(c[ni][3] + d[ni][3] + b1v, 0.0f);
            sm[oofs + (size_t)(rb + qr) * os + (col >> 1)]     = pack_h2(v0, v1);
            sm[oofs + (size_t)(rb + qr + 8) * os + (col >> 1)] = pack_h2(v2, v3);
        }
    }
}

// ================= fused MLP: 4 independent row-groups per CTA =================
__global__ void __launch_bounds__(TPB, 1) fused(
    const float* __restrict__ x, const float* __restrict__ h,
    const float* __restrict__ w1,  const float* __restrict__ b1,
    const float* __restrict__ w12, const float* __restrict__ b12,
    const float* __restrict__ w13, const float* __restrict__ b13,
    const float* __restrict__ w14, const float* __restrict__ b14,
    const float* __restrict__ w15, const float* __restrict__ b15,
    const float* __restrict__ w2,  const float* __restrict__ b2,
    float* __restrict__ out)
{
    extern __shared__ u32 sm[];
    float* smf = (float*)sm;
    u16* smh = (u16*)sm;
    const u32 sb = (u32)__cvta_generic_to_shared(sm);
    const int tid = threadIdx.x, lane = tid & 31, warp = tid >> 5;
    const int qr = lane >> 2, qc = lane & 3;
    const int grp = tid >> 7;          // 0..3 (4 warps each)
    const int wig = warp & 3;          // warp within group
    const int ltid = tid & 127;        // thread within group
    const int bid = grp + 1;           // named barrier id
    const int rb0 = grp * 32;          // group's row quarter

    // ---- weights + biases (full CTA, once) ----
    for (int i = tid; i < A_OFS; i += TPB) sm[i] = 0u;
    __syncthreads();
    for (int i = tid; i < 20000; i += TPB) {              // w1 [100][200]
        int n = i / 200, k = i % 200;
        int kk = (k < 100) ? k : k + 4;                   // h at fp16 slot 104
        smh[(W1_OFS + n * 108) * 2 + kk] = __half_as_ushort(__float2half_rn(w1[i]));
    }
    for (int i = tid; i < 5000; i += TPB) {               // w12 [50][100]
        int n = i / 100, k = i % 100;
        smh[(W12_OFS + n * 60) * 2 + k] = __half_as_ushort(__float2half_rn(w12[i]));
    }
    for (int i = tid; i < 4500; i += TPB) {               // w13 [30][150]
        int n = i / 150, k = i % 150;
        int kk = (k < 50) ? k : 64 + (k - 50);
        smh[(W13_OFS + n * 92) * 2 + kk] = __half_as_ushort(__float2half_rn(w13[i]));
    }
    for (int i = tid; i < 600; i += TPB) {                // w14 [20][30]
        int n = i / 30, k = i % 30;
        smh[(W14_OFS + n * 20) * 2 + k] = __half_as_ushort(__float2half_rn(w14[i]));
    }
    for (int i = tid; i < 4800; i += TPB) {               // w15 [40][120]
        int n = i / 120, k = i % 120;
        int kk = (k < 20) ? k : 32 + (k - 20);
        smh[(W15_OFS + n * 76) * 2 + kk] = __half_as_ushort(__float2half_rn(w15[i]));
    }
    for (int i = tid; i < 4000; i += TPB) {               // w2 [100][40]
        int n = i / 40, k = i % 40;
        smh[(W2_OFS + n * 28) * 2 + k] = __half_as_ushort(__float2half_rn(w2[i]));
    }
    for (int i = tid; i < 100; i += TPB) smf[B1_OFS + i] = b1[i];
    for (int i = tid; i < 50;  i += TPB) smf[B12_OFS + i] = b12[i];
    for (int i = tid; i < 30;  i += TPB) smf[B13_OFS + i] = b13[i];
    for (int i = tid; i < 20;  i += TPB) smf[B14_OFS + i] = b14[i];
    for (int i = tid; i < 40;  i += TPB) smf[B15_OFS + i] = b15[i];
    for (int i = tid; i < 100; i += TPB) smf[B2_OFS + i] = b2[i];
    __syncthreads();

    float p0 = 0.0f;

    for (int tile = blockIdx.x; tile < N_TILES; tile += PGRID) {
        const size_t r0 = (size_t)tile * TILE_M;
        // ---- group-local staging of its 32 rows ----
        for (int i = ltid; i < 32 * 54; i += 128) {
            int r = rb0 + i / 54, u = i % 54;
            u32* dst = sm + A_OFS + r * 108;
            size_t gr = r0 + r;
            if (u < 25) {
                float4 v = make_float4(0.f, 0.f, 0.f, 0.f);
                if (gr < N_ROWS) v = *(const float4*)(x + gr * 100 + u * 4);
                dst[2 * u]     = pack_h2(v.x, v.y);
                dst[2 * u + 1] = pack_h2(v.z, v.w);
            } else if (u == 25) {
                dst[50] = 0u; dst[51] = 0u;
            } else if (u < 51) {
                int g = u - 26;
                float4 v = make_float4(0.f, 0.f, 0.f, 0.f);
                if (gr < N_ROWS) v = *(const float4*)(h + gr * 100 + g * 4);
                dst[52 + 2 * g] = pack_h2(v.x, v.y);
                dst[53 + 2 * g] = pack_h2(v.z, v.w);
            } else {
                dst[102 + 2 * (u - 51)] = 0u;
                dst[103 + 2 * (u - 51)] = 0u;
            }
        }
        gbar(bid);
        // L1: [x|h] -> z1 (N=112), 13 steps
        layer32g(sb, sm, smf, wig, lane, rb0, W1_OFS, 108, B1_OFS,
                 A_OFS, 108, 13, 0, 0, 0, 0, Z1_OFS, 60, 7);
        gbar(bid);
        // L2: z1 -> z2 (N=64), 7 steps
        layer32g(sb, sm, smf, wig, lane, rb0, W12_OFS, 60, B12_OFS,
                 Z1_OFS, 60, 7, 0, 0, 0, 0, Z2_OFS, 36, 4);
        gbar(bid);
        // L3: [z2|h] -> z3 (N=32), 4 + 7 steps; z3 row r = Z1 + r*60
        layer16g(sb, sm, smf, wig, lane, rb0, W13_OFS, 92, B13_OFS,
                 Z2_OFS, 36, 4, A_OFS + 52, 108, 7, 32, Z1_OFS, 60, 2);
        gbar(bid);
        // L4: z3 -> z4 (N=32), 2 steps; z4 row r = Z1 + r*60 + 20
        layer16g(sb, sm, smf, wig, lane, rb0, W14_OFS, 20, B14_OFS,
                 Z1_OFS, 60, 2, 0, 0, 0, 0, Z1_OFS + 20, 60, 2);
        gbar(bid);
        // L5: [z4|h] -> z5 (N=48), 2 + 7 steps; z4 at Z1+20, stride 60
        layer32g(sb, sm, smf, wig, lane, rb0, W15_OFS, 76, B15_OFS,
                 Z1_OFS + 20, 60, 2, A_OFS + 52, 108, 7, 16, Z5_OFS, 28, 3);
        gbar(bid);
        // L6: z5 -> f (N=112, fp32, no relu): direct store + fused part0
        for (int b = wig; b < 7; b += 4) {
            int cb = b * 16;
            float c[2][2][4] = {}, d[2][2][4] = {};
            mma_b32(c, d, frag_addr(sb + Z5_OFS * 4, rb0, 28, 0, lane), (u32)(16 * 28 * 4),
                    frag_addr(sb + W2_OFS * 4, cb, 28, 0, lane), 3);
            #pragma unroll
            for (int mi = 0; mi < 2; mi++)
            #pragma unroll
            for (int ni = 0; ni < 2; ni++) {
                int col = cb + ni * 8 + 2 * qc;
                if (col >= 100) continue;
                float b0v = smf[B2_OFS + col], b1v = smf[B2_OFS + col + 1];
                #pragma unroll
                for (int hh = 0; hh < 2; hh++) {
                    size_t grow = r0 + rb0 + mi * 16 + qr + hh * 8;
                    float v0 = c[mi][ni][2 * hh]     + d[mi][ni][2 * hh]     + b0v;
                    float v1 = c[mi][ni][2 * hh + 1] + d[mi][ni][2 * hh + 1] + b1v;
                    if (grow < N_ROWS) {
                        *(float2*)(out + grow * 100 + col) = make_float2(v0, v1);
                        if (grow + 1 < N_ROWS) {
                            float2 xn = *(const float2*)(x + (grow + 1) * 100 + col);
                            float d0 = v0 - xn.x, d1 = v1 - xn.y;
                            p0 += d0 * d0 + d1 * d1;
                        }
                    }
                }
            }
        }
        gbar(bid);   // group's Z5/A reads done before its next-tile staging
    }

    // ---- CTA-wide part0 reduction ----
    #pragma unroll
    for (int o = 16; o > 0; o >>= 1) p0 += __shfl_down_sync(0xffffffffu, p0, o);
    __shared__ float red[NWARP];
    if (lane == 0) red[warp] = p0;
    __syncthreads();
    if (tid == 0) {
        float acc = 0.0f;
        #pragma unroll
        for (int i = 0; i < NWARP; i++) acc += red[i];
        atomicAdd(&g_p0, (double)acc);
    }
}

// ---------------- h statistics (high-occupancy) ----------------
#define HS_ROWS 128
__global__ void h_stats(const float* __restrict__ h) {
    const int col = threadIdx.x;
    const long long r0 = (long long)blockIdx.x * HS_ROWS;
    long long r1 = r0 + HS_ROWS; if (r1 > N_ROWS) r1 = N_ROWS;

    float csum = 0.0f, sq = 0.0f, dif = 0.0f;
    if (col < 100 && r0 < N_ROWS) {
        float prev = h[r0 * 100 + col];
        csum = prev; sq = prev * prev;
        #pragma unroll 8
        for (long long r = r0 + 1; r < r1; ++r) {
            float v = h[r * 100 + col];
            csum += v;
            sq = fmaf(v, v, sq);
            dif += fabsf(v - prev);
            prev = v;
        }
        if (r1 < N_ROWS) dif += fabsf(h[r1 * 100 + col] - prev);
        atomicAdd(&g_mu[col], (double)csum);
    }
    __shared__ float ssq[128], sdf[128];
    ssq[threadIdx.x] = sq; sdf[threadIdx.x] = dif;
    __syncthreads();
    for (int off = 64; off > 0; off >>= 1) {
        if (threadIdx.x < off) {
            ssq[threadIdx.x] += ssq[threadIdx.x + off];
            sdf[threadIdx.x] += sdf[threadIdx.x + off];
        }
        __syncthreads();
    }
    if (threadIdx.x == 0) {
        atomicAdd(&g_sq, (double)ssq[0]);
        atomicAdd(&g_diff, (double)sdf[0]);
    }
}

// ---------------- finalize ----------------
__global__ void finalize(float* __restrict__ out) {
    __shared__ double smd[128];
    const int t = threadIdx.x;
    smd[t] = (t < 100) ? fabs(g_mu[t] / (double)N_ROWS) : 0.0;
    __syncthreads();
    for (int off = 64; off > 0; off >>= 1) {
        if (t < off) smd[t] += smd[t + off];
        __syncthreads();
    }
    if (t == 0) {
        out[OUT_SCALAR + 0] = (float)(sqrt(g_p0) / (double)(N_ROWS - 1));
        out[OUT_SCALAR + 1] = (float)(smd[0] / 100.0);
        out[OUT_SCALAR + 2] = (float)fabs(g_sq / (double)N_ROWS / 100.0 - 1.0);
        out[OUT_SCALAR + 3] = (float)(g_diff / (double)(N_ROWS - 1) / 100.0);
    }
}

// ---------------- launch ----------------
extern "C" void kernel_launch(void* const* d_in, const int* in_sizes, int n_in,
                              void* d_out, int out_size) {
    const float* x   = (const float*)d_in[0];
    const float* h   = (const float*)d_in[1];
    const float* w1  = (const float*)d_in[2];
    const float* b1  = (const float*)d_in[3];
    const float* w12 = (const float*)d_in[4];
    const float* b12 = (const float*)d_in[5];
    const float* w13 = (const float*)d_in[6];
    const float* b13 = (const float*)d_in[7];
    const float* w14 = (const float*)d_in[8];
    const float* b14 = (const float*)d_in[9];
    const float* w15 = (const float*)d_in[10];
    const float* b15 = (const float*)d_in[11];
    const float* w2  = (const float*)d_in[12];
    const float* b2  = (const float*)d_in[13];
    float* out = (float*)d_out;

    (void)in_sizes; (void)n_in; (void)out_size;

    cudaFuncSetAttribute(fused, cudaFuncAttributeMaxDynamicSharedMemorySize, SMEM_B);

    init_kernel<<<1, 128>>>();
    fused<<<PGRID, TPB, SMEM_B>>>(x, h, w1, b1, w12, b12, w13, b13,
                                  w14, b14, w15, b15, w2, b2, out);
    h_stats<<<(N_ROWS + HS_ROWS - 1) / HS_ROWS, 128>>>(h);
    finalize<<<1, 128>>>(out);
}